// round 1
// baseline (speedup 1.0000x reference)
#include <cuda_runtime.h>
#include <math.h>

#define NN   200
#define DEGN 199
#define KK   20
#define MMg  10
#define HIDN 96
#define NHh  4
#define HDd  118
#define DMm  472
#define AJRn 30

#define S_OFF  0
#define H_OFF  18880000
#define HF_OFF 18899200
#define Q_OFF  18922800

// ---------------- static device scratch ----------------
__device__ float g_stat[NN*HIDN];
__device__ float g_den1[NN], g_den2[NN];
__device__ float g_hA[NN*HIDN], g_hB[NN*HIDN];
__device__ float g_hfull[NN*HDd];
__device__ float g_gcT[KK*HDd];
__device__ float g_lg[NN*HDd];
__device__ float g_W0s[HDd*DMm], g_W1s[HDd*DMm];
__device__ float g_P1[NN*DMm], g_P2[NN*DMm];
__device__ float g_khs[NHh*HDd*NN];     // [h][d][k]
__device__ float g_vh[NHh*NN*HDd];      // [h][k][d]
__device__ float g_U[NN*NHh*NN], g_V[NN*NHh*NN];   // [i][h][k]
__device__ float g_VW[(NHh*NN)*DMm];    // [h*200+k][c]
__device__ float g_Pc[40000u*800u];     // 128 MB

// ---------------- prep: edge sorts + static part of GCN ----------------
__global__ void k_prep(const float* __restrict__ x, const float* __restrict__ label,
                       const float* __restrict__ h0,
                       const float* __restrict__ w, const float* __restrict__ dv,
                       const float* __restrict__ l0w, const float* __restrict__ l0b,
                       const float* __restrict__ l1w, const float* __restrict__ l1b,
                       const float* __restrict__ l2b, const float* __restrict__ l3b,
                       const float* __restrict__ l4w, const float* __restrict__ l4b,
                       const float* __restrict__ l5w, const float* __restrict__ l5b)
{
    int i = blockIdx.x; int t = threadIdx.x;  // 128 threads
    int gi = i / MMg;
    __shared__ float a1[256], a2[256];
    __shared__ float red1[128], red2[128];
    float p1 = 0.f, p2 = 0.f;
    for (int e = t; e < 256; e += 128) {
        float v1 = -1e30f, v2 = -1e30f;
        if (e < DEGN) {
            int s = (e < i) ? e : e + 1;
            bool sm = (s / MMg) == gi;
            float d0 = dv[i*DEGN + e];
            float w0 = w[i*DEGN + e];
            if (sm) { v2 = d0; p2 += w0; } else { v1 = d0; p1 += w0; }
        }
        a1[e] = v1; a2[e] = v2;
    }
    red1[t] = p1; red2[t] = p2;
    __syncthreads();
    for (int off = 64; off > 0; off >>= 1) {
        if (t < off) { red1[t] += red1[t+off]; red2[t] += red2[t+off]; }
        __syncthreads();
    }
    if (t == 0) { g_den1[i] = red1[0]; g_den2[i] = red2[0]; }
    // bitonic sort (descending) of a1 and a2
    for (int ksz = 2; ksz <= 256; ksz <<= 1) {
        for (int jsz = ksz >> 1; jsz > 0; jsz >>= 1) {
            __syncthreads();
            for (int e = t; e < 256; e += 128) {
                int p = e ^ jsz;
                if (p > e) {
                    bool desc = ((e & ksz) == 0);
                    float av = a1[e], bv = a1[p];
                    if (desc ? (av < bv) : (av > bv)) { a1[e] = bv; a1[p] = av; }
                    float cv = a2[e], ev = a2[p];
                    if (desc ? (cv < ev) : (cv > ev)) { a2[e] = ev; a2[p] = cv; }
                }
            }
        }
    }
    __syncthreads();
    if (t < HIDN) {
        float acc = l0b[t] + l1b[t] + l2b[t] + l3b[t] + l4b[t] + l5b[t];
        acc += x[i*2+0]*l0w[0*HIDN+t] + x[i*2+1]*l0w[1*HIDN+t];
        for (int g = 0; g < KK; g++) acc += label[i*KK+g]*l1w[g*HIDN+t];
        for (int r = 0; r < AJRn; r++) acc += a1[r]*l4w[r*HIDN+t];
        for (int r = 0; r < MMg-1; r++) acc += a2[r]*l5w[r*HIDN+t];
        g_stat[i*HIDN+t] = acc;
        g_hA[i*HIDN+t] = h0[i*HIDN+t];
    }
}

// ---------------- one GCN iteration ----------------
__global__ void k_gcn(const float* __restrict__ w,
                      const float* __restrict__ l2w, const float* __restrict__ l3w,
                      const int* __restrict__ gnn_step, int iter)
{
    int i = blockIdx.x, c = threadIdx.x;  // 96 threads
    const float* hin  = (iter & 1) ? g_hB : g_hA;
    float*       hout = (iter & 1) ? g_hA : g_hB;
    if (!(iter < *gnn_step)) { hout[i*HIDN+c] = hin[i*HIDN+c]; return; }
    int gi = i / MMg;
    float acc1 = 0.f, acc2 = 0.f;
    __shared__ float sn1[HIDN], sn2[HIDN];
    for (int s = 0; s < NN; s++) {
        if (s == i) continue;
        int j = s - (s > i);
        float wv = w[i*DEGN + j];
        float hv = hin[s*HIDN + c];
        if (s / MMg == gi) acc2 += wv*hv; else acc1 += wv*hv;
    }
    sn1[c] = acc1 / g_den1[i];
    sn2[c] = acc2 / g_den2[i];
    __syncthreads();
    float o = g_stat[i*HIDN + c];
    for (int r = 0; r < HIDN; r++)
        o += sn1[r]*l2w[r*HIDN+c] + sn2[r]*l3w[r*HIDN+c];
    hout[i*HIDN + c] = fmaxf(o, 0.f);
}

// ---------------- h_full = [h + pe, x, label] ----------------
__global__ void k_hfull(const float* __restrict__ x, const float* __restrict__ label,
                        const int* __restrict__ remain)
{
    int i = blockIdx.x, t = threadIdx.x;
    if (t >= HDd) return;
    float v;
    if (t < HIDN) {
        int p = *remain;
        int k2 = t & ~1;
        double div = exp(-(double)k2 * log(10000.0) / (double)HIDN);
        double ang = (double)p * div;
        v = g_hA[i*HIDN + t] + (float)((t & 1) ? cos(ang) : sin(ang));
    } else if (t < HIDN + 2) v = x[i*2 + (t - HIDN)];
    else v = label[i*KK + (t - HIDN - 2)];
    g_hfull[i*HDd + t] = v;
}

// ---------------- gcT[g][d] = (1/M) sum_i label[i][g]*h_full[i][d] ----------------
__global__ void k_gct(const float* __restrict__ label)
{
    int g = blockIdx.x, dd = threadIdx.x;
    float acc = 0.f;
    for (int i = 0; i < NN; i++) acc += label[i*KK + g] * g_hfull[i*HDd + dd];
    g_gcT[g*HDd + dd] = acc * 0.1f;
}

// ---------------- lg[i][d] = label[i] @ gcT ----------------
__global__ void k_lg(const float* __restrict__ label)
{
    int i = blockIdx.x, dd = threadIdx.x;
    float acc = 0.f;
    for (int g = 0; g < KK; g++) acc += label[i*KK + g] * g_gcT[g*HDd + dd];
    g_lg[i*HDd + dd] = acc;
}

// ---------------- W0s/W1s = sum of the 4 row-blocks (for kv = tile(h_full,4)) ----------------
__global__ void k_wsum(const float* __restrict__ W0, const float* __restrict__ W1)
{
    int idx = blockIdx.x * blockDim.x + threadIdx.x;
    if (idx >= HDd*DMm) return;
    int d = idx / DMm, c = idx % DMm;
    g_W0s[idx] = W0[d*DMm+c] + W0[(118+d)*DMm+c] + W0[(236+d)*DMm+c] + W0[(354+d)*DMm+c];
    g_W1s[idx] = W1[d*DMm+c] + W1[(118+d)*DMm+c] + W1[(236+d)*DMm+c] + W1[(354+d)*DMm+c];
}

// ---------------- per-node projections: P1, P2, kh (scaled, transposed), vh ----------------
__global__ void k_proj(const float* __restrict__ W0, const float* __restrict__ B0,
                       const float* __restrict__ B1)
{
    int i = blockIdx.x, t = threadIdx.x;  // 128 threads
    __shared__ float hf[HDd], lgs[HDd];
    if (t < HDd) { hf[t] = g_hfull[i*HDd + t]; lgs[t] = g_lg[i*HDd + t]; }
    __syncthreads();
    const float scale = 1.0f / sqrtf((float)HDd);
    for (int c = t; c < DMm; c += 128) {
        float p1 = B0[c], p2 = 0.f, kf = B0[c], vf = B1[c];
        for (int d = 0; d < HDd; d++) {
            float hv = hf[d], lv = lgs[d];
            p1 += hv * W0[d*DMm + c]       + lv * W0[(236+d)*DMm + c];
            p2 += hv * W0[(118+d)*DMm + c] + lv * W0[(354+d)*DMm + c];
            kf += hv * g_W0s[d*DMm + c];
            vf += hv * g_W1s[d*DMm + c];
        }
        g_P1[i*DMm + c] = p1;
        g_P2[i*DMm + c] = p2;
        int h = c / HDd, dd = c % HDd;
        g_khs[(h*HDd + dd)*NN + i] = kf * scale;
        g_vh[(h*NN + i)*HDd + dd] = vf;
    }
}

// ---------------- U[i][h][k] = P1[i]_h . kh_h[k] ;  V = P2 . kh ----------------
__global__ void k_uv()
{
    int i = blockIdx.x, h = blockIdx.y, t = threadIdx.x;  // 256 threads
    __shared__ float s1[HDd], s2[HDd];
    if (t < HDd) {
        s1[t] = g_P1[i*DMm + h*HDd + t];
        s2[t] = g_P2[i*DMm + h*HDd + t];
    }
    __syncthreads();
    if (t < NN) {
        float u = 0.f, v = 0.f;
        for (int d = 0; d < HDd; d++) {
            float kv = g_khs[(h*HDd + d)*NN + t];
            u += s1[d] * kv;
            v += s2[d] * kv;
        }
        g_U[(i*NHh + h)*NN + t] = u;
        g_V[(i*NHh + h)*NN + t] = v;
    }
}

// ---------------- VW[h*200+k][c] = vh[h][k] @ W3[h*118:(h+1)*118] ----------------
__global__ void k_vw(const float* __restrict__ W3)
{
    int row = blockIdx.x, t = threadIdx.x;  // 128 threads
    int h = row / NN, k = row % NN;
    __shared__ float vr[HDd];
    if (t < HDd) vr[t] = g_vh[(h*NN + k)*HDd + t];
    __syncthreads();
    for (int c = t; c < DMm; c += 128) {
        float acc = 0.f;
        for (int d = 0; d < HDd; d++) acc += vr[d] * W3[(h*HDd + d)*DMm + c];
        g_VW[row*DMm + c] = acc;
    }
}

// ---------------- softmax pair kernel: Pc[b][h*200+k] = p1 + p2 ----------------
__global__ void k_prob()
{
    int b = blockIdx.x;
    int i = b / NN, j = b % NN;
    int h = threadIdx.x >> 5;
    int lane = threadIdx.x & 31;
    const float* Ui = g_U + (i*NHh + h)*NN;
    const float* Vi = g_V + (i*NHh + h)*NN;
    const float* Uj = g_U + (j*NHh + h)*NN;
    const float* Vj = g_V + (j*NHh + h)*NN;
    float s1[7], s2[7];
    float m1 = -1e30f, m2 = -1e30f;
    #pragma unroll
    for (int r = 0; r < 7; r++) {
        int k = lane + 32*r;
        if (k < NN) {
            float a = Ui[k] + Vj[k];
            float c = Uj[k] + Vi[k];
            s1[r] = a; s2[r] = c;
            m1 = fmaxf(m1, a); m2 = fmaxf(m2, c);
        } else { s1[r] = -1e30f; s2[r] = -1e30f; }
    }
    #pragma unroll
    for (int o = 16; o > 0; o >>= 1) {
        m1 = fmaxf(m1, __shfl_xor_sync(0xffffffffu, m1, o));
        m2 = fmaxf(m2, __shfl_xor_sync(0xffffffffu, m2, o));
    }
    float e1[7], e2[7];
    float sum1 = 0.f, sum2 = 0.f;
    #pragma unroll
    for (int r = 0; r < 7; r++) {
        int k = lane + 32*r;
        if (k < NN) {
            e1[r] = __expf(s1[r] - m1);
            e2[r] = __expf(s2[r] - m2);
            sum1 += e1[r]; sum2 += e2[r];
        } else { e1[r] = 0.f; e2[r] = 0.f; }
    }
    #pragma unroll
    for (int o = 16; o > 0; o >>= 1) {
        sum1 += __shfl_xor_sync(0xffffffffu, sum1, o);
        sum2 += __shfl_xor_sync(0xffffffffu, sum2, o);
    }
    float inv1 = 1.f / sum1, inv2 = 1.f / sum2;
    #pragma unroll
    for (int r = 0; r < 7; r++) {
        int k = lane + 32*r;
        if (k < NN)
            g_Pc[(size_t)b*800 + h*200 + k] = e1[r]*inv1 + e2[r]*inv2;
    }
}

// ---------------- S = Pc (40000x800) @ VW (800x472) + 2*b3 ----------------
__global__ void k_sgemm(const float* __restrict__ B3, float* __restrict__ out)
{
    __shared__ float As[16][64];
    __shared__ float Bs[16][64];
    int tid = threadIdx.x;
    int tx = tid & 15, ty = tid >> 4;
    int bm = blockIdx.x * 64, bn = blockIdx.y * 64;
    float acc[4][4];
    #pragma unroll
    for (int r = 0; r < 4; r++)
        #pragma unroll
        for (int c = 0; c < 4; c++) acc[r][c] = 0.f;
    for (int kk = 0; kk < 800; kk += 16) {
        #pragma unroll
        for (int r = 0; r < 4; r++) {
            int li = tid + r*256;
            int m = li >> 4, k = li & 15;
            As[k][m] = g_Pc[(size_t)(bm + m)*800 + kk + k];
        }
        #pragma unroll
        for (int r = 0; r < 4; r++) {
            int li = tid + r*256;
            int k = li >> 6, n = li & 63;
            int col = bn + n;
            Bs[k][n] = (col < DMm) ? g_VW[(kk + k)*DMm + col] : 0.f;
        }
        __syncthreads();
        #pragma unroll
        for (int k = 0; k < 16; k++) {
            float a0 = As[k][ty*4+0], a1 = As[k][ty*4+1], a2 = As[k][ty*4+2], a3 = As[k][ty*4+3];
            float b0 = Bs[k][tx*4+0], b1 = Bs[k][tx*4+1], b2 = Bs[k][tx*4+2], b3 = Bs[k][tx*4+3];
            acc[0][0] += a0*b0; acc[0][1] += a0*b1; acc[0][2] += a0*b2; acc[0][3] += a0*b3;
            acc[1][0] += a1*b0; acc[1][1] += a1*b1; acc[1][2] += a1*b2; acc[1][3] += a1*b3;
            acc[2][0] += a2*b0; acc[2][1] += a2*b1; acc[2][2] += a2*b2; acc[2][3] += a2*b3;
            acc[3][0] += a3*b0; acc[3][1] += a3*b1; acc[3][2] += a3*b2; acc[3][3] += a3*b3;
        }
        __syncthreads();
    }
    #pragma unroll
    for (int r = 0; r < 4; r++) {
        int row = bm + ty*4 + r;
        #pragma unroll
        for (int c = 0; c < 4; c++) {
            int col = bn + tx*4 + c;
            if (col < DMm)
                out[(size_t)row*DMm + col] = acc[r][c] + 2.f*B3[col];
        }
    }
}

// ---------------- Q_sa = (relu(S@v1w+v1b)@v2w + v2b) ----------------
__global__ void k_qsa(const float* __restrict__ v1w, const float* __restrict__ v1b,
                      const float* __restrict__ v2w, const float* __restrict__ v2b,
                      const float* __restrict__ S, float* __restrict__ qout)
{
    int b = blockIdx.x, t = threadIdx.x;  // 64 threads
    __shared__ float sS[64];
    __shared__ float red[64];
    float acc = 0.f;
    for (int r0 = 0; r0 < DMm; r0 += 64) {
        int r = r0 + t;
        sS[t] = (r < DMm) ? S[(size_t)b*DMm + r] : 0.f;
        __syncthreads();
        int lim = DMm - r0; if (lim > 64) lim = 64;
        if (t < 48) {
            for (int rr = 0; rr < lim; rr++)
                acc += sS[rr] * v1w[(r0 + rr)*48 + t];
        }
        __syncthreads();
    }
    float val = 0.f;
    if (t < 48) {
        float hv = fmaxf(acc + v1b[t], 0.f);
        val = hv * v2w[t];
    }
    red[t] = val;
    __syncthreads();
    for (int off = 32; off > 0; off >>= 1) {
        if (t < off) red[t] += red[t + off];
        __syncthreads();
    }
    if (t == 0) qout[b] = red[0] + v2b[0];
}

// ---------------- tail: copy h, h_full into output ----------------
__global__ void k_tail(float* __restrict__ out)
{
    int idx = blockIdx.x * blockDim.x + threadIdx.x;
    if (idx < NN*HIDN) out[H_OFF + idx] = g_hA[idx];
    else if (idx < NN*HIDN + NN*HDd) {
        int j = idx - NN*HIDN;
        out[HF_OFF + j] = g_hfull[j];
    }
}

// ---------------- launcher ----------------
extern "C" void kernel_launch(void* const* d_in, const int* in_sizes, int n_in,
                              void* d_out, int out_size)
{
    const float* x     = (const float*)d_in[0];
    const float* label = (const float*)d_in[1];
    const float* h0    = (const float*)d_in[2];
    const float* w     = (const float*)d_in[3];
    const float* dv    = (const float*)d_in[4];
    const float* l0w   = (const float*)d_in[5];
    const float* l0b   = (const float*)d_in[6];
    const float* l1w   = (const float*)d_in[7];
    const float* l1b   = (const float*)d_in[8];
    const float* l2w   = (const float*)d_in[9];
    const float* l2b   = (const float*)d_in[10];
    const float* l3w   = (const float*)d_in[11];
    const float* l3b   = (const float*)d_in[12];
    const float* l4w   = (const float*)d_in[13];
    const float* l4b   = (const float*)d_in[14];
    const float* l5w   = (const float*)d_in[15];
    const float* l5b   = (const float*)d_in[16];
    const float* W0    = (const float*)d_in[17];
    const float* B0    = (const float*)d_in[18];
    const float* W1    = (const float*)d_in[19];
    const float* B1    = (const float*)d_in[20];
    const float* W3    = (const float*)d_in[21];
    const float* B3    = (const float*)d_in[22];
    const float* v1w   = (const float*)d_in[23];
    const float* v1b   = (const float*)d_in[24];
    const float* v2w   = (const float*)d_in[25];
    const float* v2b   = (const float*)d_in[26];
    const int* gnn_step = (const int*)d_in[27];
    const int* remain   = (const int*)d_in[29];
    float* out = (float*)d_out;

    k_prep<<<NN, 128>>>(x, label, h0, w, dv, l0w, l0b, l1w, l1b, l2b, l3b, l4w, l4b, l5w, l5b);
    for (int it = 0; it < 8; it++)
        k_gcn<<<NN, HIDN>>>(w, l2w, l3w, gnn_step, it);
    k_hfull<<<NN, 128>>>(x, label, remain);
    k_gct<<<KK, HDd>>>(label);
    k_lg<<<NN, HDd>>>(label);
    k_wsum<<<(HDd*DMm + 255)/256, 256>>>(W0, W1);
    k_proj<<<NN, 128>>>(W0, B0, B1);
    dim3 guv(NN, NHh);
    k_uv<<<guv, 256>>>();
    k_vw<<<NHh*NN, 128>>>(W3);
    k_prob<<<40000, 128>>>();
    dim3 gs(625, 8);
    k_sgemm<<<gs, 256>>>(B3, out);
    k_qsa<<<40000, 64>>>(v1w, v1b, v2w, v2b, out, out + Q_OFF);
    k_tail<<<(NN*HIDN + NN*HDd + 255)/256, 256>>>(out);
}

// round 4
// speedup vs baseline: 1.8564x; 1.8564x over previous
#include <cuda_runtime.h>
#include <math.h>

#define NN   200
#define DEGN 199
#define KK   20
#define MMg  10
#define HIDN 96
#define NHh  4
#define HDd  118
#define DMm  472
#define AJRn 30

#define S_OFF  0
#define H_OFF  18880000
#define HF_OFF 18899200
#define Q_OFF  18922800

// ---------------- static device scratch ----------------
__device__ float g_stat[NN*HIDN];
__device__ float g_den1[NN], g_den2[NN];
__device__ float g_hA[NN*HIDN], g_hB[NN*HIDN];
__device__ float g_hfull[NN*HDd];
__device__ float g_gcT[KK*HDd];
__device__ float g_lg[NN*HDd];
__device__ float g_W0s[HDd*DMm], g_W1s[HDd*DMm];
__device__ float g_P1[NN*DMm], g_P2[NN*DMm];
__device__ float g_khs[NHh*HDd*NN];     // [h][d][k]
__device__ float g_vh[NHh*NN*HDd];      // [h][k][d]
__device__ float g_U[NN*NHh*NN], g_V[NN*NHh*NN];   // [i][h][k]
__device__ float g_VW[(NHh*NN)*DMm];    // [h*200+k][c]
__device__ float g_Pc[40000u*800u];     // 128 MB

// ---------------- prep: edge sorts + static part of GCN ----------------
__global__ void k_prep(const float* __restrict__ x, const float* __restrict__ label,
                       const float* __restrict__ h0,
                       const float* __restrict__ w, const float* __restrict__ dv,
                       const float* __restrict__ l0w, const float* __restrict__ l0b,
                       const float* __restrict__ l1w, const float* __restrict__ l1b,
                       const float* __restrict__ l2b, const float* __restrict__ l3b,
                       const float* __restrict__ l4w, const float* __restrict__ l4b,
                       const float* __restrict__ l5w, const float* __restrict__ l5b)
{
    int i = blockIdx.x; int t = threadIdx.x;  // 128 threads
    int gi = i / MMg;
    __shared__ float a1[256], a2[256];
    __shared__ float red1[128], red2[128];
    float p1 = 0.f, p2 = 0.f;
    for (int e = t; e < 256; e += 128) {
        float v1 = -1e30f, v2 = -1e30f;
        if (e < DEGN) {
            int s = (e < i) ? e : e + 1;
            bool sm = (s / MMg) == gi;
            float d0 = dv[i*DEGN + e];
            float w0 = w[i*DEGN + e];
            if (sm) { v2 = d0; p2 += w0; } else { v1 = d0; p1 += w0; }
        }
        a1[e] = v1; a2[e] = v2;
    }
    red1[t] = p1; red2[t] = p2;
    __syncthreads();
    for (int off = 64; off > 0; off >>= 1) {
        if (t < off) { red1[t] += red1[t+off]; red2[t] += red2[t+off]; }
        __syncthreads();
    }
    if (t == 0) { g_den1[i] = red1[0]; g_den2[i] = red2[0]; }
    // bitonic sort (descending) of a1 and a2
    for (int ksz = 2; ksz <= 256; ksz <<= 1) {
        for (int jsz = ksz >> 1; jsz > 0; jsz >>= 1) {
            __syncthreads();
            for (int e = t; e < 256; e += 128) {
                int p = e ^ jsz;
                if (p > e) {
                    bool desc = ((e & ksz) == 0);
                    float av = a1[e], bv = a1[p];
                    if (desc ? (av < bv) : (av > bv)) { a1[e] = bv; a1[p] = av; }
                    float cv = a2[e], ev = a2[p];
                    if (desc ? (cv < ev) : (cv > ev)) { a2[e] = ev; a2[p] = cv; }
                }
            }
        }
    }
    __syncthreads();
    if (t < HIDN) {
        float acc = l0b[t] + l1b[t] + l2b[t] + l3b[t] + l4b[t] + l5b[t];
        acc += x[i*2+0]*l0w[0*HIDN+t] + x[i*2+1]*l0w[1*HIDN+t];
        for (int g = 0; g < KK; g++) acc += label[i*KK+g]*l1w[g*HIDN+t];
        for (int r = 0; r < AJRn; r++) acc += a1[r]*l4w[r*HIDN+t];
        for (int r = 0; r < MMg-1; r++) acc += a2[r]*l5w[r*HIDN+t];
        g_stat[i*HIDN+t] = acc;
        g_hA[i*HIDN+t] = h0[i*HIDN+t];
    }
}

// ---------------- one GCN iteration ----------------
__global__ void k_gcn(const float* __restrict__ w,
                      const float* __restrict__ l2w, const float* __restrict__ l3w,
                      const int* __restrict__ gnn_step, int iter)
{
    int i = blockIdx.x, c = threadIdx.x;  // 96 threads
    const float* hin  = (iter & 1) ? g_hB : g_hA;
    float*       hout = (iter & 1) ? g_hA : g_hB;
    if (!(iter < *gnn_step)) { hout[i*HIDN+c] = hin[i*HIDN+c]; return; }
    int gi = i / MMg;
    float acc1 = 0.f, acc2 = 0.f;
    __shared__ float sn1[HIDN], sn2[HIDN];
    for (int s = 0; s < NN; s++) {
        if (s == i) continue;
        int j = s - (s > i);
        float wv = w[i*DEGN + j];
        float hv = hin[s*HIDN + c];
        if (s / MMg == gi) acc2 += wv*hv; else acc1 += wv*hv;
    }
    sn1[c] = acc1 / g_den1[i];
    sn2[c] = acc2 / g_den2[i];
    __syncthreads();
    float o = g_stat[i*HIDN + c];
    for (int r = 0; r < HIDN; r++)
        o += sn1[r]*l2w[r*HIDN+c] + sn2[r]*l3w[r*HIDN+c];
    hout[i*HIDN + c] = fmaxf(o, 0.f);
}

// ---------------- h_full = [h + pe, x, label] ----------------
__global__ void k_hfull(const float* __restrict__ x, const float* __restrict__ label,
                        const int* __restrict__ remain)
{
    int i = blockIdx.x, t = threadIdx.x;
    if (t >= HDd) return;
    float v;
    if (t < HIDN) {
        int p = *remain;
        int k2 = t & ~1;
        double div = exp(-(double)k2 * log(10000.0) / (double)HIDN);
        double ang = (double)p * div;
        v = g_hA[i*HIDN + t] + (float)((t & 1) ? cos(ang) : sin(ang));
    } else if (t < HIDN + 2) v = x[i*2 + (t - HIDN)];
    else v = label[i*KK + (t - HIDN - 2)];
    g_hfull[i*HDd + t] = v;
}

// ---------------- gcT[g][d] = (1/M) sum_i label[i][g]*h_full[i][d] ----------------
__global__ void k_gct(const float* __restrict__ label)
{
    int g = blockIdx.x, dd = threadIdx.x;
    float acc = 0.f;
    for (int i = 0; i < NN; i++) acc += label[i*KK + g] * g_hfull[i*HDd + dd];
    g_gcT[g*HDd + dd] = acc * 0.1f;
}

// ---------------- lg[i][d] = label[i] @ gcT ----------------
__global__ void k_lg(const float* __restrict__ label)
{
    int i = blockIdx.x, dd = threadIdx.x;
    float acc = 0.f;
    for (int g = 0; g < KK; g++) acc += label[i*KK + g] * g_gcT[g*HDd + dd];
    g_lg[i*HDd + dd] = acc;
}

// ---------------- W0s/W1s = sum of the 4 row-blocks ----------------
__global__ void k_wsum(const float* __restrict__ W0, const float* __restrict__ W1)
{
    int idx = blockIdx.x * blockDim.x + threadIdx.x;
    if (idx >= HDd*DMm) return;
    int d = idx / DMm, c = idx % DMm;
    g_W0s[idx] = W0[d*DMm+c] + W0[(118+d)*DMm+c] + W0[(236+d)*DMm+c] + W0[(354+d)*DMm+c];
    g_W1s[idx] = W1[d*DMm+c] + W1[(118+d)*DMm+c] + W1[(236+d)*DMm+c] + W1[(354+d)*DMm+c];
}

// ---------------- per-node projections: P1, P2, kh (scaled, transposed), vh ----------------
__global__ void k_proj(const float* __restrict__ W0, const float* __restrict__ B0,
                       const float* __restrict__ B1)
{
    int i = blockIdx.x, t = threadIdx.x;  // 128 threads
    __shared__ float hf[HDd], lgs[HDd];
    if (t < HDd) { hf[t] = g_hfull[i*HDd + t]; lgs[t] = g_lg[i*HDd + t]; }
    __syncthreads();
    const float scale = 1.0f / sqrtf((float)HDd);
    for (int c = t; c < DMm; c += 128) {
        float p1 = B0[c], p2 = 0.f, kf = B0[c], vf = B1[c];
        for (int d = 0; d < HDd; d++) {
            float hv = hf[d], lv = lgs[d];
            p1 += hv * W0[d*DMm + c]       + lv * W0[(236+d)*DMm + c];
            p2 += hv * W0[(118+d)*DMm + c] + lv * W0[(354+d)*DMm + c];
            kf += hv * g_W0s[d*DMm + c];
            vf += hv * g_W1s[d*DMm + c];
        }
        g_P1[i*DMm + c] = p1;
        g_P2[i*DMm + c] = p2;
        int h = c / HDd, dd = c % HDd;
        g_khs[(h*HDd + dd)*NN + i] = kf * scale;
        g_vh[(h*NN + i)*HDd + dd] = vf;
    }
}

// ---------------- U[i][h][k] = P1[i]_h . kh_h[k] ;  V = P2 . kh ----------------
__global__ void k_uv()
{
    int i = blockIdx.x, h = blockIdx.y, t = threadIdx.x;  // 256 threads
    __shared__ float s1[HDd], s2[HDd];
    if (t < HDd) {
        s1[t] = g_P1[i*DMm + h*HDd + t];
        s2[t] = g_P2[i*DMm + h*HDd + t];
    }
    __syncthreads();
    if (t < NN) {
        float u = 0.f, v = 0.f;
        for (int d = 0; d < HDd; d++) {
            float kv = g_khs[(h*HDd + d)*NN + t];
            u += s1[d] * kv;
            v += s2[d] * kv;
        }
        g_U[(i*NHh + h)*NN + t] = u;
        g_V[(i*NHh + h)*NN + t] = v;
    }
}

// ---------------- VW[h*200+k][c] = vh[h][k] @ W3[h*118:(h+1)*118] ----------------
__global__ void k_vw(const float* __restrict__ W3)
{
    int row = blockIdx.x, t = threadIdx.x;  // 128 threads
    int h = row / NN, k = row % NN;
    __shared__ float vr[HDd];
    if (t < HDd) vr[t] = g_vh[(h*NN + k)*HDd + t];
    __syncthreads();
    for (int c = t; c < DMm; c += 128) {
        float acc = 0.f;
        for (int d = 0; d < HDd; d++) acc += vr[d] * W3[(h*HDd + d)*DMm + c];
        g_VW[row*DMm + c] = acc;
    }
}

// ---------------- softmax pair kernel: Pc[b][h*200+k] = p1 + p2 ----------------
__global__ void k_prob()
{
    int b = blockIdx.x;
    int i = b / NN, j = b % NN;
    int h = threadIdx.x >> 5;
    int lane = threadIdx.x & 31;
    const float* Ui = g_U + (i*NHh + h)*NN;
    const float* Vi = g_V + (i*NHh + h)*NN;
    const float* Uj = g_U + (j*NHh + h)*NN;
    const float* Vj = g_V + (j*NHh + h)*NN;
    float s1[7], s2[7];
    float m1 = -1e30f, m2 = -1e30f;
    #pragma unroll
    for (int r = 0; r < 7; r++) {
        int k = lane + 32*r;
        if (k < NN) {
            float a = Ui[k] + Vj[k];
            float c = Uj[k] + Vi[k];
            s1[r] = a; s2[r] = c;
            m1 = fmaxf(m1, a); m2 = fmaxf(m2, c);
        } else { s1[r] = -1e30f; s2[r] = -1e30f; }
    }
    #pragma unroll
    for (int o = 16; o > 0; o >>= 1) {
        m1 = fmaxf(m1, __shfl_xor_sync(0xffffffffu, m1, o));
        m2 = fmaxf(m2, __shfl_xor_sync(0xffffffffu, m2, o));
    }
    float e1[7], e2[7];
    float sum1 = 0.f, sum2 = 0.f;
    #pragma unroll
    for (int r = 0; r < 7; r++) {
        int k = lane + 32*r;
        if (k < NN) {
            e1[r] = __expf(s1[r] - m1);
            e2[r] = __expf(s2[r] - m2);
            sum1 += e1[r]; sum2 += e2[r];
        } else { e1[r] = 0.f; e2[r] = 0.f; }
    }
    #pragma unroll
    for (int o = 16; o > 0; o >>= 1) {
        sum1 += __shfl_xor_sync(0xffffffffu, sum1, o);
        sum2 += __shfl_xor_sync(0xffffffffu, sum2, o);
    }
    float inv1 = 1.f / sum1, inv2 = 1.f / sum2;
    #pragma unroll
    for (int r = 0; r < 7; r++) {
        int k = lane + 32*r;
        if (k < NN)
            g_Pc[(size_t)b*800 + h*200 + k] = e1[r]*inv1 + e2[r]*inv2;
    }
}

// ---------------- tf32 helpers ----------------
__device__ __forceinline__ unsigned cvt_tf32(float x) {
    unsigned r;
    asm("cvt.rna.tf32.f32 %0, %1;" : "=r"(r) : "f"(x));
    return r;
}
__device__ __forceinline__ void mma_tf32(float* c, const unsigned* a, const unsigned* b) {
    asm("mma.sync.aligned.m16n8k8.row.col.f32.tf32.tf32.f32 "
        "{%0,%1,%2,%3},{%4,%5,%6,%7},{%8,%9},{%0,%1,%2,%3};"
        : "+f"(c[0]), "+f"(c[1]), "+f"(c[2]), "+f"(c[3])
        : "r"(a[0]), "r"(a[1]), "r"(a[2]), "r"(a[3]), "r"(b[0]), "r"(b[1]));
}

// ---------------- S = Pc (40000x800) @ VW (800x472) + 2*b3 — tf32 MMA ----------------
// grid: (8 n-tiles, 313 m-tiles), 256 threads (8 warps, 4x2 warp grid, 32x32/warp)
__global__ __launch_bounds__(256) void k_mma(const float* __restrict__ B3,
                                             float* __restrict__ out)
{
    __shared__ float As[2][16][132];
    __shared__ float Bs[2][16][68];
    int t = threadIdx.x;
    int w = t >> 5, lane = t & 31;
    int g = lane >> 2, tg = lane & 3;
    int wm = (w >> 1) * 32, wn = (w & 1) * 32;
    int bm = blockIdx.y * 128, bn = blockIdx.x * 64;

    float acc[2][4][4];
    #pragma unroll
    for (int mm = 0; mm < 2; mm++)
        #pragma unroll
        for (int nn = 0; nn < 4; nn++)
            #pragma unroll
            for (int q = 0; q < 4; q++) acc[mm][nn][q] = 0.f;

    // ---- prologue: load tile 0 into buffer 0 ----
    {
        #pragma unroll
        for (int l = 0; l < 2; l++) {
            int li = t + l * 256;
            int m = li >> 2, kq = (li & 3) * 4;
            int row = bm + m;
            float4 v = make_float4(0.f, 0.f, 0.f, 0.f);
            if (row < 40000)
                v = *(const float4*)&g_Pc[(size_t)row * 800 + kq];
            As[0][kq + 0][m] = v.x; As[0][kq + 1][m] = v.y;
            As[0][kq + 2][m] = v.z; As[0][kq + 3][m] = v.w;
        }
        #pragma unroll
        for (int l = 0; l < 4; l++) {
            int li = t + l * 256;
            int k = li >> 6, n = li & 63;
            int col = bn + n;
            Bs[0][k][n] = (col < DMm) ? g_VW[k * DMm + col] : 0.f;
        }
    }
    __syncthreads();

    for (int kt = 0; kt < 50; kt++) {
        int cur = kt & 1;
        float4 av[2];
        float bv[4];
        if (kt < 49) {
            int k0 = (kt + 1) * 16;
            #pragma unroll
            for (int l = 0; l < 2; l++) {
                int li = t + l * 256;
                int m = li >> 2, kq = (li & 3) * 4;
                int row = bm + m;
                av[l] = make_float4(0.f, 0.f, 0.f, 0.f);
                if (row < 40000)
                    av[l] = *(const float4*)&g_Pc[(size_t)row * 800 + k0 + kq];
            }
            #pragma unroll
            for (int l = 0; l < 4; l++) {
                int li = t + l * 256;
                int k = li >> 6, n = li & 63;
                int col = bn + n;
                bv[l] = (col < DMm) ? g_VW[(k0 + k) * DMm + col] : 0.f;
            }
        }
        // ---- compute on cur ----
        #pragma unroll
        for (int ks = 0; ks < 2; ks++) {
            int kb = ks * 8;
            unsigned af[2][4], bf[4][2];
            #pragma unroll
            for (int mm = 0; mm < 2; mm++) {
                int r0 = wm + mm * 16 + g;
                af[mm][0] = cvt_tf32(As[cur][kb + tg][r0]);
                af[mm][1] = cvt_tf32(As[cur][kb + tg][r0 + 8]);
                af[mm][2] = cvt_tf32(As[cur][kb + tg + 4][r0]);
                af[mm][3] = cvt_tf32(As[cur][kb + tg + 4][r0 + 8]);
            }
            #pragma unroll
            for (int nn = 0; nn < 4; nn++) {
                int c0 = wn + nn * 8 + g;
                bf[nn][0] = cvt_tf32(Bs[cur][kb + tg][c0]);
                bf[nn][1] = cvt_tf32(Bs[cur][kb + tg + 4][c0]);
            }
            #pragma unroll
            for (int mm = 0; mm < 2; mm++)
                #pragma unroll
                for (int nn = 0; nn < 4; nn++)
                    mma_tf32(acc[mm][nn], af[mm], bf[nn]);
        }
        if (kt < 49) {
            int nxt = cur ^ 1;
            #pragma unroll
            for (int l = 0; l < 2; l++) {
                int li = t + l * 256;
                int m = li >> 2, kq = (li & 3) * 4;
                As[nxt][kq + 0][m] = av[l].x; As[nxt][kq + 1][m] = av[l].y;
                As[nxt][kq + 2][m] = av[l].z; As[nxt][kq + 3][m] = av[l].w;
            }
            #pragma unroll
            for (int l = 0; l < 4; l++) {
                int li = t + l * 256;
                int k = li >> 6, n = li & 63;
                Bs[nxt][k][n] = bv[l];
            }
        }
        __syncthreads();
    }

    // ---- epilogue ----
    #pragma unroll
    for (int mm = 0; mm < 2; mm++) {
        #pragma unroll
        for (int nn = 0; nn < 4; nn++) {
            int r = bm + wm + mm * 16 + g;
            int c = bn + wn + nn * 8 + tg * 2;
            if (r < 40000) {
                if (c < DMm)     out[(size_t)r * DMm + c]     = acc[mm][nn][0] + 2.f * B3[c];
                if (c + 1 < DMm) out[(size_t)r * DMm + c + 1] = acc[mm][nn][1] + 2.f * B3[c + 1];
            }
            if (r + 8 < 40000) {
                if (c < DMm)     out[(size_t)(r + 8) * DMm + c]     = acc[mm][nn][2] + 2.f * B3[c];
                if (c + 1 < DMm) out[(size_t)(r + 8) * DMm + c + 1] = acc[mm][nn][3] + 2.f * B3[c + 1];
            }
        }
    }
}

// ---------------- Q_sa: warp per row ----------------
__global__ __launch_bounds__(256) void k_qsa(const float* __restrict__ v1w,
                                             const float* __restrict__ v1b,
                                             const float* __restrict__ v2w,
                                             const float* __restrict__ v2b,
                                             const float* __restrict__ S,
                                             float* __restrict__ qout)
{
    int wid = threadIdx.x >> 5, lane = threadIdx.x & 31;
    int b = blockIdx.x * 8 + wid;
    const float* Srow = S + (size_t)b * DMm;
    float acc0 = 0.f, acc1 = 0.f;
    for (int r = 0; r < DMm; r += 4) {
        float4 s4 = *(const float4*)(Srow + r);
        acc0 += s4.x * v1w[(r + 0) * 48 + lane];
        acc0 += s4.y * v1w[(r + 1) * 48 + lane];
        acc0 += s4.z * v1w[(r + 2) * 48 + lane];
        acc0 += s4.w * v1w[(r + 3) * 48 + lane];
        if (lane < 16) {
            acc1 += s4.x * v1w[(r + 0) * 48 + 32 + lane];
            acc1 += s4.y * v1w[(r + 1) * 48 + 32 + lane];
            acc1 += s4.z * v1w[(r + 2) * 48 + 32 + lane];
            acc1 += s4.w * v1w[(r + 3) * 48 + 32 + lane];
        }
    }
    float val = fmaxf(acc0 + v1b[lane], 0.f) * v2w[lane];
    if (lane < 16)
        val += fmaxf(acc1 + v1b[32 + lane], 0.f) * v2w[32 + lane];
    #pragma unroll
    for (int o = 16; o > 0; o >>= 1)
        val += __shfl_xor_sync(0xffffffffu, val, o);
    if (lane == 0) qout[b] = val + v2b[0];
}

// ---------------- tail: copy h, h_full into output ----------------
__global__ void k_tail(float* __restrict__ out)
{
    int idx = blockIdx.x * blockDim.x + threadIdx.x;
    if (idx < NN*HIDN) out[H_OFF + idx] = g_hA[idx];
    else if (idx < NN*HIDN + NN*HDd) {
        int j = idx - NN*HIDN;
        out[HF_OFF + j] = g_hfull[j];
    }
}

// ---------------- launcher ----------------
extern "C" void kernel_launch(void* const* d_in, const int* in_sizes, int n_in,
                              void* d_out, int out_size)
{
    const float* x     = (const float*)d_in[0];
    const float* label = (const float*)d_in[1];
    const float* h0    = (const float*)d_in[2];
    const float* w     = (const float*)d_in[3];
    const float* dv    = (const float*)d_in[4];
    const float* l0w   = (const float*)d_in[5];
    const float* l0b   = (const float*)d_in[6];
    const float* l1w   = (const float*)d_in[7];
    const float* l1b   = (const float*)d_in[8];
    const float* l2w   = (const float*)d_in[9];
    const float* l2b   = (const float*)d_in[10];
    const float* l3w   = (const float*)d_in[11];
    const float* l3b   = (const float*)d_in[12];
    const float* l4w   = (const float*)d_in[13];
    const float* l4b   = (const float*)d_in[14];
    const float* l5w   = (const float*)d_in[15];
    const float* l5b   = (const float*)d_in[16];
    const float* W0    = (const float*)d_in[17];
    const float* B0    = (const float*)d_in[18];
    const float* W1    = (const float*)d_in[19];
    const float* B1    = (const float*)d_in[20];
    const float* W3    = (const float*)d_in[21];
    const float* B3    = (const float*)d_in[22];
    const float* v1w   = (const float*)d_in[23];
    const float* v1b   = (const float*)d_in[24];
    const float* v2w   = (const float*)d_in[25];
    const float* v2b   = (const float*)d_in[26];
    const int* gnn_step = (const int*)d_in[27];
    const int* remain   = (const int*)d_in[29];
    float* out = (float*)d_out;

    k_prep<<<NN, 128>>>(x, label, h0, w, dv, l0w, l0b, l1w, l1b, l2b, l3b, l4w, l4b, l5w, l5b);
    for (int it = 0; it < 8; it++)
        k_gcn<<<NN, HIDN>>>(w, l2w, l3w, gnn_step, it);
    k_hfull<<<NN, 128>>>(x, label, remain);
    k_gct<<<KK, HDd>>>(label);
    k_lg<<<NN, HDd>>>(label);
    k_wsum<<<(HDd*DMm + 255)/256, 256>>>(W0, W1);
    k_proj<<<NN, 128>>>(W0, B0, B1);
    dim3 guv(NN, NHh);
    k_uv<<<guv, 256>>>();
    k_vw<<<NHh*NN, 128>>>(W3);
    k_prob<<<40000, 128>>>();
    dim3 gs(8, 313);
    k_mma<<<gs, 256>>>(B3, out);
    k_qsa<<<5000, 256>>>(v1w, v1b, v2w, v2b, out, out + Q_OFF);
    k_tail<<<(NN*HIDN + NN*HDd + 255)/256, 256>>>(out);
}

// round 6
// speedup vs baseline: 2.6731x; 1.4400x over previous
#include <cuda_runtime.h>
#include <cuda_fp16.h>
#include <math.h>

#define NN   200
#define DEGN 199
#define KK   20
#define MMg  10
#define HIDN 96
#define NHh  4
#define HDd  118
#define DMm  472
#define AJRn 30

#define S_OFF  0
#define H_OFF  18880000
#define HF_OFF 18899200
#define Q_OFF  18922800

// ---------------- static device scratch ----------------
__device__ float g_stat[NN*HIDN];
__device__ float g_den1[NN], g_den2[NN];
__device__ float g_hA[NN*HIDN], g_hB[NN*HIDN];
__device__ float g_hfull[NN*HDd];
__device__ float g_gcT[KK*HDd];
__device__ float g_lg[NN*HDd];
__device__ float g_W0s[HDd*DMm], g_W1s[HDd*DMm];
__device__ float g_P1[NN*DMm], g_P2[NN*DMm];
__device__ float g_khs[NHh*HDd*NN];     // [h][d][k]
__device__ float g_vh[NHh*NN*HDd];      // [h][k][d]
__device__ float g_U[NN*NHh*NN], g_V[NN*NHh*NN];   // [i][h][k]
__device__ __half g_VWh[800*DMm];       // [h*200+k][c]  fp16
__device__ __half g_Pch[40000u*800u];   // 64 MB fp16

// ---------------- prep: edge sorts + static part of GCN ----------------
__global__ void k_prep(const float* __restrict__ x, const float* __restrict__ label,
                       const float* __restrict__ h0,
                       const float* __restrict__ w, const float* __restrict__ dv,
                       const float* __restrict__ l0w, const float* __restrict__ l0b,
                       const float* __restrict__ l1w, const float* __restrict__ l1b,
                       const float* __restrict__ l2b, const float* __restrict__ l3b,
                       const float* __restrict__ l4w, const float* __restrict__ l4b,
                       const float* __restrict__ l5w, const float* __restrict__ l5b)
{
    int i = blockIdx.x; int t = threadIdx.x;  // 128 threads
    int gi = i / MMg;
    __shared__ float a1[256], a2[256];
    __shared__ float red1[128], red2[128];
    float p1 = 0.f, p2 = 0.f;
    for (int e = t; e < 256; e += 128) {
        float v1 = -1e30f, v2 = -1e30f;
        if (e < DEGN) {
            int s = (e < i) ? e : e + 1;
            bool sm = (s / MMg) == gi;
            float d0 = dv[i*DEGN + e];
            float w0 = w[i*DEGN + e];
            if (sm) { v2 = d0; p2 += w0; } else { v1 = d0; p1 += w0; }
        }
        a1[e] = v1; a2[e] = v2;
    }
    red1[t] = p1; red2[t] = p2;
    __syncthreads();
    for (int off = 64; off > 0; off >>= 1) {
        if (t < off) { red1[t] += red1[t+off]; red2[t] += red2[t+off]; }
        __syncthreads();
    }
    if (t == 0) { g_den1[i] = red1[0]; g_den2[i] = red2[0]; }
    for (int ksz = 2; ksz <= 256; ksz <<= 1) {
        for (int jsz = ksz >> 1; jsz > 0; jsz >>= 1) {
            __syncthreads();
            for (int e = t; e < 256; e += 128) {
                int p = e ^ jsz;
                if (p > e) {
                    bool desc = ((e & ksz) == 0);
                    float av = a1[e], bv = a1[p];
                    if (desc ? (av < bv) : (av > bv)) { a1[e] = bv; a1[p] = av; }
                    float cv = a2[e], ev = a2[p];
                    if (desc ? (cv < ev) : (cv > ev)) { a2[e] = ev; a2[p] = cv; }
                }
            }
        }
    }
    __syncthreads();
    if (t < HIDN) {
        float acc = l0b[t] + l1b[t] + l2b[t] + l3b[t] + l4b[t] + l5b[t];
        acc += x[i*2+0]*l0w[0*HIDN+t] + x[i*2+1]*l0w[1*HIDN+t];
        for (int g = 0; g < KK; g++) acc += label[i*KK+g]*l1w[g*HIDN+t];
        for (int r = 0; r < AJRn; r++) acc += a1[r]*l4w[r*HIDN+t];
        for (int r = 0; r < MMg-1; r++) acc += a2[r]*l5w[r*HIDN+t];
        g_stat[i*HIDN+t] = acc;
        g_hA[i*HIDN+t] = h0[i*HIDN+t];
    }
}

// ---------------- one GCN iteration ----------------
__global__ void k_gcn(const float* __restrict__ w,
                      const float* __restrict__ l2w, const float* __restrict__ l3w,
                      const int* __restrict__ gnn_step, int iter)
{
    int i = blockIdx.x, c = threadIdx.x;  // 96 threads
    const float* hin  = (iter & 1) ? g_hB : g_hA;
    float*       hout = (iter & 1) ? g_hA : g_hB;
    if (!(iter < *gnn_step)) { hout[i*HIDN+c] = hin[i*HIDN+c]; return; }
    int gi = i / MMg;
    float acc1 = 0.f, acc2 = 0.f;
    __shared__ float sn1[HIDN], sn2[HIDN];
    for (int s = 0; s < NN; s++) {
        if (s == i) continue;
        int j = s - (s > i);
        float wv = w[i*DEGN + j];
        float hv = hin[s*HIDN + c];
        if (s / MMg == gi) acc2 += wv*hv; else acc1 += wv*hv;
    }
    sn1[c] = acc1 / g_den1[i];
    sn2[c] = acc2 / g_den2[i];
    __syncthreads();
    float o = g_stat[i*HIDN + c];
    for (int r = 0; r < HIDN; r++)
        o += sn1[r]*l2w[r*HIDN+c] + sn2[r]*l3w[r*HIDN+c];
    hout[i*HIDN + c] = fmaxf(o, 0.f);
}

// ---------------- h_full = [h + pe, x, label] ----------------
__global__ void k_hfull(const float* __restrict__ x, const float* __restrict__ label,
                        const int* __restrict__ remain)
{
    int i = blockIdx.x, t = threadIdx.x;
    if (t >= HDd) return;
    float v;
    if (t < HIDN) {
        int p = *remain;
        int k2 = t & ~1;
        double div = exp(-(double)k2 * log(10000.0) / (double)HIDN);
        double ang = (double)p * div;
        v = g_hA[i*HIDN + t] + (float)((t & 1) ? cos(ang) : sin(ang));
    } else if (t < HIDN + 2) v = x[i*2 + (t - HIDN)];
    else v = label[i*KK + (t - HIDN - 2)];
    g_hfull[i*HDd + t] = v;
}

__global__ void k_gct(const float* __restrict__ label)
{
    int g = blockIdx.x, dd = threadIdx.x;
    float acc = 0.f;
    for (int i = 0; i < NN; i++) acc += label[i*KK + g] * g_hfull[i*HDd + dd];
    g_gcT[g*HDd + dd] = acc * 0.1f;
}

__global__ void k_lg(const float* __restrict__ label)
{
    int i = blockIdx.x, dd = threadIdx.x;
    float acc = 0.f;
    for (int g = 0; g < KK; g++) acc += label[i*KK + g] * g_gcT[g*HDd + dd];
    g_lg[i*HDd + dd] = acc;
}

__global__ void k_wsum(const float* __restrict__ W0, const float* __restrict__ W1)
{
    int idx = blockIdx.x * blockDim.x + threadIdx.x;
    if (idx >= HDd*DMm) return;
    int d = idx / DMm, c = idx % DMm;
    g_W0s[idx] = W0[d*DMm+c] + W0[(118+d)*DMm+c] + W0[(236+d)*DMm+c] + W0[(354+d)*DMm+c];
    g_W1s[idx] = W1[d*DMm+c] + W1[(118+d)*DMm+c] + W1[(236+d)*DMm+c] + W1[(354+d)*DMm+c];
}

// ---------------- per-node projections ----------------
__global__ void k_proj(const float* __restrict__ W0, const float* __restrict__ B0,
                       const float* __restrict__ B1)
{
    int i = blockIdx.x, t = threadIdx.x;  // 128 threads
    __shared__ float hf[HDd], lgs[HDd];
    if (t < HDd) { hf[t] = g_hfull[i*HDd + t]; lgs[t] = g_lg[i*HDd + t]; }
    __syncthreads();
    const float scale = 1.0f / sqrtf((float)HDd);
    for (int c = t; c < DMm; c += 128) {
        float p1 = B0[c], p2 = 0.f, kf = B0[c], vf = B1[c];
        for (int d = 0; d < HDd; d++) {
            float hv = hf[d], lv = lgs[d];
            p1 += hv * W0[d*DMm + c]       + lv * W0[(236+d)*DMm + c];
            p2 += hv * W0[(118+d)*DMm + c] + lv * W0[(354+d)*DMm + c];
            kf += hv * g_W0s[d*DMm + c];
            vf += hv * g_W1s[d*DMm + c];
        }
        g_P1[i*DMm + c] = p1;
        g_P2[i*DMm + c] = p2;
        int h = c / HDd, dd = c % HDd;
        g_khs[(h*HDd + dd)*NN + i] = kf * scale;
        g_vh[(h*NN + i)*HDd + dd] = vf;
    }
}

// ---------------- U/V score components ----------------
__global__ void k_uv()
{
    int i = blockIdx.x, h = blockIdx.y, t = threadIdx.x;  // 256 threads
    __shared__ float s1[HDd], s2[HDd];
    if (t < HDd) {
        s1[t] = g_P1[i*DMm + h*HDd + t];
        s2[t] = g_P2[i*DMm + h*HDd + t];
    }
    __syncthreads();
    if (t < NN) {
        float u = 0.f, v = 0.f;
        for (int d = 0; d < HDd; d++) {
            float kv = g_khs[(h*HDd + d)*NN + t];
            u += s1[d] * kv;
            v += s2[d] * kv;
        }
        g_U[(i*NHh + h)*NN + t] = u;
        g_V[(i*NHh + h)*NN + t] = v;
    }
}

// ---------------- VW (fp16) ----------------
__global__ void k_vw(const float* __restrict__ W3)
{
    int row = blockIdx.x, t = threadIdx.x;  // 128 threads
    int h = row / NN, k = row % NN;
    __shared__ float vr[HDd];
    if (t < HDd) vr[t] = g_vh[(h*NN + k)*HDd + t];
    __syncthreads();
    for (int c = t; c < DMm; c += 128) {
        float acc = 0.f;
        for (int d = 0; d < HDd; d++) acc += vr[d] * W3[(h*HDd + d)*DMm + c];
        g_VWh[row*DMm + c] = __float2half_rn(acc);
    }
}

// ---------------- softmax pair kernel -> fp16 Pc ----------------
__global__ void k_prob()
{
    int b = blockIdx.x;
    int i = b / NN, j = b % NN;
    int h = threadIdx.x >> 5;
    int lane = threadIdx.x & 31;
    const float* Ui = g_U + (i*NHh + h)*NN;
    const float* Vi = g_V + (i*NHh + h)*NN;
    const float* Uj = g_U + (j*NHh + h)*NN;
    const float* Vj = g_V + (j*NHh + h)*NN;
    float s1[7], s2[7];
    float m1 = -1e30f, m2 = -1e30f;
    #pragma unroll
    for (int r = 0; r < 7; r++) {
        int k = lane + 32*r;
        if (k < NN) {
            float a = Ui[k] + Vj[k];
            float c = Uj[k] + Vi[k];
            s1[r] = a; s2[r] = c;
            m1 = fmaxf(m1, a); m2 = fmaxf(m2, c);
        } else { s1[r] = -1e30f; s2[r] = -1e30f; }
    }
    #pragma unroll
    for (int o = 16; o > 0; o >>= 1) {
        m1 = fmaxf(m1, __shfl_xor_sync(0xffffffffu, m1, o));
        m2 = fmaxf(m2, __shfl_xor_sync(0xffffffffu, m2, o));
    }
    float e1[7], e2[7];
    float sum1 = 0.f, sum2 = 0.f;
    #pragma unroll
    for (int r = 0; r < 7; r++) {
        int k = lane + 32*r;
        if (k < NN) {
            e1[r] = __expf(s1[r] - m1);
            e2[r] = __expf(s2[r] - m2);
            sum1 += e1[r]; sum2 += e2[r];
        } else { e1[r] = 0.f; e2[r] = 0.f; }
    }
    #pragma unroll
    for (int o = 16; o > 0; o >>= 1) {
        sum1 += __shfl_xor_sync(0xffffffffu, sum1, o);
        sum2 += __shfl_xor_sync(0xffffffffu, sum2, o);
    }
    float inv1 = 1.f / sum1, inv2 = 1.f / sum2;
    #pragma unroll
    for (int r = 0; r < 7; r++) {
        int k = lane + 32*r;
        if (k < NN)
            g_Pch[(size_t)b*800 + h*200 + k] = __float2half_rn(e1[r]*inv1 + e2[r]*inv2);
    }
}

// ---------------- fp16 MMA GEMM: S = Pc(40000x800) @ VW(800x472) + 2*b3 ----------------
#define BMt 128
#define BNt 64
#define BKt 32
#define A_STRIDE 40                  // halfs (32 + 8 pad) -> 80B rows, conflict-free
#define B_STRIDE 72                  // halfs (64 + 8 pad) -> 144B rows, conflict-free
#define A_BYTES  (BMt * A_STRIDE * 2)   // 10240
#define B_BYTES  (BKt * B_STRIDE * 2)   // 4608
#define STG_BYTES (A_BYTES + B_BYTES)   // 14848
#define KT 25

__device__ __forceinline__ void cp_async16(unsigned dst, const void* src, int src_bytes) {
    asm volatile("cp.async.cg.shared.global [%0], [%1], 16, %2;\n"
                 :: "r"(dst), "l"(src), "r"(src_bytes));
}
__device__ __forceinline__ void cp_commit() {
    asm volatile("cp.async.commit_group;\n");
}
__device__ __forceinline__ void cp_wait1() {
    asm volatile("cp.async.wait_group 1;\n");
}
__device__ __forceinline__ void ldmA4(unsigned* r, unsigned addr) {
    asm volatile("ldmatrix.sync.aligned.m8n8.x4.shared.b16 {%0,%1,%2,%3}, [%4];"
                 : "=r"(r[0]), "=r"(r[1]), "=r"(r[2]), "=r"(r[3]) : "r"(addr));
}
__device__ __forceinline__ void ldmBT4(unsigned* r, unsigned addr) {
    asm volatile("ldmatrix.sync.aligned.m8n8.x4.trans.shared.b16 {%0,%1,%2,%3}, [%4];"
                 : "=r"(r[0]), "=r"(r[1]), "=r"(r[2]), "=r"(r[3]) : "r"(addr));
}
__device__ __forceinline__ void mma_f16(float* c, const unsigned* a, const unsigned* b) {
    asm volatile("mma.sync.aligned.m16n8k16.row.col.f32.f16.f16.f32 "
                 "{%0,%1,%2,%3},{%4,%5,%6,%7},{%8,%9},{%0,%1,%2,%3};"
                 : "+f"(c[0]), "+f"(c[1]), "+f"(c[2]), "+f"(c[3])
                 : "r"(a[0]), "r"(a[1]), "r"(a[2]), "r"(a[3]), "r"(b[0]), "r"(b[1]));
}

__device__ __forceinline__ void load_stage(unsigned sbase, int stage, int k0,
                                           int bm, int bn, int t)
{
    unsigned sa = sbase + stage * STG_BYTES;
    unsigned sb = sa + A_BYTES;
    #pragma unroll
    for (int p = 0; p < 2; p++) {
        int li = t + p * 256;
        int row = li >> 2, ch = li & 3;
        int grow = bm + row;
        bool ok = (grow < 40000);
        const __half* src = g_Pch + (size_t)(ok ? grow : 0) * 800 + k0 + ch * 8;
        cp_async16(sa + (unsigned)(row * A_STRIDE + ch * 8) * 2, src, ok ? 16 : 0);
    }
    {
        int k = t >> 3, ch = t & 7;
        int col = bn + ch * 8;
        int rem = DMm - col;
        int sz = (rem >= 8) ? 16 : ((rem > 0) ? rem * 2 : 0);
        const __half* src = g_VWh + (size_t)(k0 + k) * DMm + ((col < DMm) ? col : 0);
        cp_async16(sb + (unsigned)(k * B_STRIDE + ch * 8) * 2, src, sz);
    }
}

__global__ __launch_bounds__(256) void k_mma(const float* __restrict__ B3,
                                             float* __restrict__ out)
{
    __shared__ __align__(16) unsigned char smem[3 * STG_BYTES];
    unsigned sbase = (unsigned)__cvta_generic_to_shared(smem);

    int t = threadIdx.x;
    int w = t >> 5, lane = t & 31;
    int wm = (w & 3) * 32;          // warp m offset
    int wn = (w >> 2) * 32;         // warp n offset
    int bm = blockIdx.y * BMt, bn = blockIdx.x * BNt;

    float acc[2][4][4];
    #pragma unroll
    for (int mm = 0; mm < 2; mm++)
        #pragma unroll
        for (int nn = 0; nn < 4; nn++)
            #pragma unroll
            for (int q = 0; q < 4; q++) acc[mm][nn][q] = 0.f;

    // per-lane ldmatrix address components
    int arow = wm + (lane & 15);
    int acb  = (lane >> 4) * 8;
    int bkl  = (lane & 7) + (lane & 8);
    int bnl  = wn + ((lane >> 4) * 8);

    load_stage(sbase, 0, 0, bm, bn, t);  cp_commit();
    load_stage(sbase, 1, 32, bm, bn, t); cp_commit();

    for (int kt = 0; kt < KT; kt++) {
        cp_wait1();
        __syncthreads();
        // issue prefetch for kt+2
        if (kt + 2 < KT) load_stage(sbase, (kt + 2) % 3, (kt + 2) * BKt, bm, bn, t);
        cp_commit();
        // compute on stage kt%3
        unsigned sa = sbase + (kt % 3) * STG_BYTES;
        unsigned sb = sa + A_BYTES;
        #pragma unroll
        for (int ks = 0; ks < 2; ks++) {
            unsigned af[2][4], bf[2][4];
            ldmA4(af[0], sa + (unsigned)((arow)      * A_STRIDE + ks * 16 + acb) * 2);
            ldmA4(af[1], sa + (unsigned)((arow + 16) * A_STRIDE + ks * 16 + acb) * 2);
            ldmBT4(bf[0], sb + (unsigned)((ks * 16 + bkl) * B_STRIDE + bnl) * 2);
            ldmBT4(bf[1], sb + (unsigned)((ks * 16 + bkl) * B_STRIDE + bnl + 16) * 2);
            #pragma unroll
            for (int mm = 0; mm < 2; mm++) {
                mma_f16(acc[mm][0], af[mm], bf[0] + 0);
                mma_f16(acc[mm][1], af[mm], bf[0] + 2);
                mma_f16(acc[mm][2], af[mm], bf[1] + 0);
                mma_f16(acc[mm][3], af[mm], bf[1] + 2);
            }
        }
        __syncthreads();
    }

    // epilogue: C frag (m16n8): rows lane/4, lane/4+8; cols (lane&3)*2, +1
    int r0 = bm + wm + (lane >> 2);
    int c0 = bn + wn + (lane & 3) * 2;
    #pragma unroll
    for (int mm = 0; mm < 2; mm++) {
        int rbase = r0 + mm * 16;
        #pragma unroll
        for (int nn = 0; nn < 4; nn++) {
            int c = c0 + nn * 8;
            if (c < DMm) {
                float b3a = 2.f * B3[c], b3b = 2.f * B3[c + 1];
                if (rbase < 40000) {
                    float2 v = make_float2(acc[mm][nn][0] + b3a, acc[mm][nn][1] + b3b);
                    *(float2*)&out[(size_t)rbase * DMm + c] = v;
                }
                if (rbase + 8 < 40000) {
                    float2 v = make_float2(acc[mm][nn][2] + b3a, acc[mm][nn][3] + b3b);
                    *(float2*)&out[(size_t)(rbase + 8) * DMm + c] = v;
                }
            }
        }
    }
}

// ---------------- Q_sa: warp per row ----------------
__global__ __launch_bounds__(256) void k_qsa(const float* __restrict__ v1w,
                                             const float* __restrict__ v1b,
                                             const float* __restrict__ v2w,
                                             const float* __restrict__ v2b,
                                             const float* __restrict__ S,
                                             float* __restrict__ qout)
{
    int wid = threadIdx.x >> 5, lane = threadIdx.x & 31;
    int b = blockIdx.x * 8 + wid;
    const float* Srow = S + (size_t)b * DMm;
    float acc0 = 0.f, acc1 = 0.f;
    for (int r = 0; r < DMm; r += 4) {
        float4 s4 = *(const float4*)(Srow + r);
        acc0 += s4.x * v1w[(r + 0) * 48 + lane];
        acc0 += s4.y * v1w[(r + 1) * 48 + lane];
        acc0 += s4.z * v1w[(r + 2) * 48 + lane];
        acc0 += s4.w * v1w[(r + 3) * 48 + lane];
        if (lane < 16) {
            acc1 += s4.x * v1w[(r + 0) * 48 + 32 + lane];
            acc1 += s4.y * v1w[(r + 1) * 48 + 32 + lane];
            acc1 += s4.z * v1w[(r + 2) * 48 + 32 + lane];
            acc1 += s4.w * v1w[(r + 3) * 48 + 32 + lane];
        }
    }
    float val = fmaxf(acc0 + v1b[lane], 0.f) * v2w[lane];
    if (lane < 16)
        val += fmaxf(acc1 + v1b[32 + lane], 0.f) * v2w[32 + lane];
    #pragma unroll
    for (int o = 16; o > 0; o >>= 1)
        val += __shfl_xor_sync(0xffffffffu, val, o);
    if (lane == 0) qout[b] = val + v2b[0];
}

// ---------------- tail: copy h, h_full into output ----------------
__global__ void k_tail(float* __restrict__ out)
{
    int idx = blockIdx.x * blockDim.x + threadIdx.x;
    if (idx < NN*HIDN) out[H_OFF + idx] = g_hA[idx];
    else if (idx < NN*HIDN + NN*HDd) {
        int j = idx - NN*HIDN;
        out[HF_OFF + j] = g_hfull[j];
    }
}

// ---------------- launcher ----------------
extern "C" void kernel_launch(void* const* d_in, const int* in_sizes, int n_in,
                              void* d_out, int out_size)
{
    const float* x     = (const float*)d_in[0];
    const float* label = (const float*)d_in[1];
    const float* h0    = (const float*)d_in[2];
    const float* w     = (const float*)d_in[3];
    const float* dv    = (const float*)d_in[4];
    const float* l0w   = (const float*)d_in[5];
    const float* l0b   = (const float*)d_in[6];
    const float* l1w   = (const float*)d_in[7];
    const float* l1b   = (const float*)d_in[8];
    const float* l2w   = (const float*)d_in[9];
    const float* l2b   = (const float*)d_in[10];
    const float* l3w   = (const float*)d_in[11];
    const float* l3b   = (const float*)d_in[12];
    const float* l4w   = (const float*)d_in[13];
    const float* l4b   = (const float*)d_in[14];
    const float* l5w   = (const float*)d_in[15];
    const float* l5b   = (const float*)d_in[16];
    const float* W0    = (const float*)d_in[17];
    const float* B0    = (const float*)d_in[18];
    const float* W1    = (const float*)d_in[19];
    const float* B1    = (const float*)d_in[20];
    const float* W3    = (const float*)d_in[21];
    const float* B3    = (const float*)d_in[22];
    const float* v1w   = (const float*)d_in[23];
    const float* v1b   = (const float*)d_in[24];
    const float* v2w   = (const float*)d_in[25];
    const float* v2b   = (const float*)d_in[26];
    const int* gnn_step = (const int*)d_in[27];
    const int* remain   = (const int*)d_in[29];
    float* out = (float*)d_out;

    k_prep<<<NN, 128>>>(x, label, h0, w, dv, l0w, l0b, l1w, l1b, l2b, l3b, l4w, l4b, l5w, l5b);
    for (int it = 0; it < 8; it++)
        k_gcn<<<NN, HIDN>>>(w, l2w, l3w, gnn_step, it);
    k_hfull<<<NN, 128>>>(x, label, remain);
    k_gct<<<KK, HDd>>>(label);
    k_lg<<<NN, HDd>>>(label);
    k_wsum<<<(HDd*DMm + 255)/256, 256>>>(W0, W1);
    k_proj<<<NN, 128>>>(W0, B0, B1);
    dim3 guv(NN, NHh);
    k_uv<<<guv, 256>>>();
    k_vw<<<NHh*NN, 128>>>(W3);
    k_prob<<<40000, 128>>>();
    dim3 gs(8, 313);
    k_mma<<<gs, 256>>>(B3, out);
    k_qsa<<<5000, 256>>>(v1w, v1b, v2w, v2b, out, out + Q_OFF);
    k_tail<<<(NN*HIDN + NN*HDd + 255)/256, 256>>>(out);
}

// round 7
// speedup vs baseline: 2.7116x; 1.0144x over previous
#include <cuda_runtime.h>
#include <cuda_fp16.h>
#include <math.h>

#define NN   200
#define DEGN 199
#define KK   20
#define MMg  10
#define HIDN 96
#define NHh  4
#define HDd  118
#define DMm  472
#define AJRn 30

#define S_OFF  0
#define H_OFF  18880000
#define HF_OFF 18899200
#define Q_OFF  18922800

// ---------------- static device scratch ----------------
__device__ float g_stat[NN*HIDN];
__device__ float g_den1[NN], g_den2[NN];
__device__ float g_hA[NN*HIDN], g_hB[NN*HIDN];
__device__ float g_hfull[NN*HDd];
__device__ float g_gcT[KK*HDd];
__device__ float g_lg[NN*HDd];
__device__ float g_W0s[HDd*DMm], g_W1s[HDd*DMm];
__device__ float g_P1[NN*DMm], g_P2[NN*DMm];
__device__ float g_khs[NHh*HDd*NN];     // [h][d][k]
__device__ float g_vh[NHh*NN*HDd];      // [h][k][d]
__device__ float g_U[NN*NHh*NN], g_V[NN*NHh*NN];   // [(i*4+h)][k]
__device__ float g_EU[NN*NHh*NN], g_EV[NN*NHh*NN]; // exp(U - rowmax), exp(V - rowmax)
__device__ __half g_VWh[800*DMm];       // [h*200+k][c]  fp16
__device__ __half g_Pch[40000u*800u];   // 64 MB fp16

// ---------------- prep: edge sorts + static part of GCN ----------------
__global__ void k_prep(const float* __restrict__ x, const float* __restrict__ label,
                       const float* __restrict__ h0,
                       const float* __restrict__ w, const float* __restrict__ dv,
                       const float* __restrict__ l0w, const float* __restrict__ l0b,
                       const float* __restrict__ l1w, const float* __restrict__ l1b,
                       const float* __restrict__ l2b, const float* __restrict__ l3b,
                       const float* __restrict__ l4w, const float* __restrict__ l4b,
                       const float* __restrict__ l5w, const float* __restrict__ l5b)
{
    int i = blockIdx.x; int t = threadIdx.x;  // 128 threads
    int gi = i / MMg;
    __shared__ float a1[256], a2[256];
    __shared__ float red1[128], red2[128];
    float p1 = 0.f, p2 = 0.f;
    for (int e = t; e < 256; e += 128) {
        float v1 = -1e30f, v2 = -1e30f;
        if (e < DEGN) {
            int s = (e < i) ? e : e + 1;
            bool sm = (s / MMg) == gi;
            float d0 = dv[i*DEGN + e];
            float w0 = w[i*DEGN + e];
            if (sm) { v2 = d0; p2 += w0; } else { v1 = d0; p1 += w0; }
        }
        a1[e] = v1; a2[e] = v2;
    }
    red1[t] = p1; red2[t] = p2;
    __syncthreads();
    for (int off = 64; off > 0; off >>= 1) {
        if (t < off) { red1[t] += red1[t+off]; red2[t] += red2[t+off]; }
        __syncthreads();
    }
    if (t == 0) { g_den1[i] = red1[0]; g_den2[i] = red2[0]; }
    for (int ksz = 2; ksz <= 256; ksz <<= 1) {
        for (int jsz = ksz >> 1; jsz > 0; jsz >>= 1) {
            __syncthreads();
            for (int e = t; e < 256; e += 128) {
                int p = e ^ jsz;
                if (p > e) {
                    bool desc = ((e & ksz) == 0);
                    float av = a1[e], bv = a1[p];
                    if (desc ? (av < bv) : (av > bv)) { a1[e] = bv; a1[p] = av; }
                    float cv = a2[e], ev = a2[p];
                    if (desc ? (cv < ev) : (cv > ev)) { a2[e] = ev; a2[p] = cv; }
                }
            }
        }
    }
    __syncthreads();
    if (t < HIDN) {
        float acc = l0b[t] + l1b[t] + l2b[t] + l3b[t] + l4b[t] + l5b[t];
        acc += x[i*2+0]*l0w[0*HIDN+t] + x[i*2+1]*l0w[1*HIDN+t];
        for (int g = 0; g < KK; g++) acc += label[i*KK+g]*l1w[g*HIDN+t];
        for (int r = 0; r < AJRn; r++) acc += a1[r]*l4w[r*HIDN+t];
        for (int r = 0; r < MMg-1; r++) acc += a2[r]*l5w[r*HIDN+t];
        g_stat[i*HIDN+t] = acc;
        g_hA[i*HIDN+t] = h0[i*HIDN+t];
    }
}

// ---------------- one GCN iteration ----------------
__global__ void k_gcn(const float* __restrict__ w,
                      const float* __restrict__ l2w, const float* __restrict__ l3w,
                      const int* __restrict__ gnn_step, int iter)
{
    int i = blockIdx.x, c = threadIdx.x;  // 96 threads
    const float* hin  = (iter & 1) ? g_hB : g_hA;
    float*       hout = (iter & 1) ? g_hA : g_hB;
    if (!(iter < *gnn_step)) { hout[i*HIDN+c] = hin[i*HIDN+c]; return; }
    int gi = i / MMg;
    float acc1 = 0.f, acc2 = 0.f;
    __shared__ float sn1[HIDN], sn2[HIDN];
    for (int s = 0; s < NN; s++) {
        if (s == i) continue;
        int j = s - (s > i);
        float wv = w[i*DEGN + j];
        float hv = hin[s*HIDN + c];
        if (s / MMg == gi) acc2 += wv*hv; else acc1 += wv*hv;
    }
    sn1[c] = acc1 / g_den1[i];
    sn2[c] = acc2 / g_den2[i];
    __syncthreads();
    float o = g_stat[i*HIDN + c];
    for (int r = 0; r < HIDN; r++)
        o += sn1[r]*l2w[r*HIDN+c] + sn2[r]*l3w[r*HIDN+c];
    hout[i*HIDN + c] = fmaxf(o, 0.f);
}

// ---------------- h_full = [h + pe, x, label] ----------------
__global__ void k_hfull(const float* __restrict__ x, const float* __restrict__ label,
                        const int* __restrict__ remain)
{
    int i = blockIdx.x, t = threadIdx.x;
    if (t >= HDd) return;
    float v;
    if (t < HIDN) {
        int p = *remain;
        int k2 = t & ~1;
        double div = exp(-(double)k2 * log(10000.0) / (double)HIDN);
        double ang = (double)p * div;
        v = g_hA[i*HIDN + t] + (float)((t & 1) ? cos(ang) : sin(ang));
    } else if (t < HIDN + 2) v = x[i*2 + (t - HIDN)];
    else v = label[i*KK + (t - HIDN - 2)];
    g_hfull[i*HDd + t] = v;
}

__global__ void k_gct(const float* __restrict__ label)
{
    int g = blockIdx.x, dd = threadIdx.x;
    float acc = 0.f;
    for (int i = 0; i < NN; i++) acc += label[i*KK + g] * g_hfull[i*HDd + dd];
    g_gcT[g*HDd + dd] = acc * 0.1f;
}

__global__ void k_lg(const float* __restrict__ label)
{
    int i = blockIdx.x, dd = threadIdx.x;
    float acc = 0.f;
    for (int g = 0; g < KK; g++) acc += label[i*KK + g] * g_gcT[g*HDd + dd];
    g_lg[i*HDd + dd] = acc;
}

__global__ void k_wsum(const float* __restrict__ W0, const float* __restrict__ W1)
{
    int idx = blockIdx.x * blockDim.x + threadIdx.x;
    if (idx >= HDd*DMm) return;
    int d = idx / DMm, c = idx % DMm;
    g_W0s[idx] = W0[d*DMm+c] + W0[(118+d)*DMm+c] + W0[(236+d)*DMm+c] + W0[(354+d)*DMm+c];
    g_W1s[idx] = W1[d*DMm+c] + W1[(118+d)*DMm+c] + W1[(236+d)*DMm+c] + W1[(354+d)*DMm+c];
}

// ---------------- per-node projections ----------------
__global__ void k_proj(const float* __restrict__ W0, const float* __restrict__ B0,
                       const float* __restrict__ B1)
{
    int i = blockIdx.x, t = threadIdx.x;  // 128 threads
    __shared__ float hf[HDd], lgs[HDd];
    if (t < HDd) { hf[t] = g_hfull[i*HDd + t]; lgs[t] = g_lg[i*HDd + t]; }
    __syncthreads();
    const float scale = 1.0f / sqrtf((float)HDd);
    for (int c = t; c < DMm; c += 128) {
        float p1 = B0[c], p2 = 0.f, kf = B0[c], vf = B1[c];
        for (int d = 0; d < HDd; d++) {
            float hv = hf[d], lv = lgs[d];
            p1 += hv * W0[d*DMm + c]       + lv * W0[(236+d)*DMm + c];
            p2 += hv * W0[(118+d)*DMm + c] + lv * W0[(354+d)*DMm + c];
            kf += hv * g_W0s[d*DMm + c];
            vf += hv * g_W1s[d*DMm + c];
        }
        g_P1[i*DMm + c] = p1;
        g_P2[i*DMm + c] = p2;
        int h = c / HDd, dd = c % HDd;
        g_khs[(h*HDd + dd)*NN + i] = kf * scale;
        g_vh[(h*NN + i)*HDd + dd] = vf;
    }
}

// ---------------- U/V score components ----------------
__global__ void k_uv()
{
    int i = blockIdx.x, h = blockIdx.y, t = threadIdx.x;  // 256 threads
    __shared__ float s1[HDd], s2[HDd];
    if (t < HDd) {
        s1[t] = g_P1[i*DMm + h*HDd + t];
        s2[t] = g_P2[i*DMm + h*HDd + t];
    }
    __syncthreads();
    if (t < NN) {
        float u = 0.f, v = 0.f;
        for (int d = 0; d < HDd; d++) {
            float kv = g_khs[(h*HDd + d)*NN + t];
            u += s1[d] * kv;
            v += s2[d] * kv;
        }
        g_U[(i*NHh + h)*NN + t] = u;
        g_V[(i*NHh + h)*NN + t] = v;
    }
}

// ---------------- EU/EV: rowwise exp(x - rowmax) over the 800 U,V rows ----------------
// grid 100 x 256 threads: 8 warps/block, warp handles one row (both U and V)
__global__ void k_expuv()
{
    int row = blockIdx.x * 8 + (threadIdx.x >> 5);   // 0..799
    int lane = threadIdx.x & 31;
    const float* Ur = g_U + row * NN;
    const float* Vr = g_V + row * NN;
    float u[7], v[7];
    float mu = -1e30f, mv = -1e30f;
    #pragma unroll
    for (int r = 0; r < 7; r++) {
        int k = lane + 32*r;
        if (k < NN) {
            u[r] = Ur[k]; v[r] = Vr[k];
            mu = fmaxf(mu, u[r]); mv = fmaxf(mv, v[r]);
        } else { u[r] = -1e30f; v[r] = -1e30f; }
    }
    #pragma unroll
    for (int o = 16; o > 0; o >>= 1) {
        mu = fmaxf(mu, __shfl_xor_sync(0xffffffffu, mu, o));
        mv = fmaxf(mv, __shfl_xor_sync(0xffffffffu, mv, o));
    }
    #pragma unroll
    for (int r = 0; r < 7; r++) {
        int k = lane + 32*r;
        if (k < NN) {
            g_EU[row * NN + k] = __expf(u[r] - mu);
            g_EV[row * NN + k] = __expf(v[r] - mv);
        }
    }
}

// ---------------- pair-softmax via separable exps: NO exp in this kernel ----------------
// p1[k] = EU_i[k]*EV_j[k] / Σ ;  p2[k] = EU_j[k]*EV_i[k] / Σ ; Pc = p1 + p2
// 8 warps: warp (h, side). side1 writes its normalized part to smem, side0 adds.
__global__ __launch_bounds__(256) void k_prob()
{
    int b = blockIdx.x;
    int i = b / NN, j = b % NN;
    int w = threadIdx.x >> 5;
    int lane = threadIdx.x & 31;
    int h = w & 3, side = w >> 2;
    __shared__ float s[800];

    int ra = (side ? j : i) * NHh + h;   // EU row
    int rb = (side ? i : j) * NHh + h;   // EV row
    const float* EA = g_EU + ra * NN;
    const float* EB = g_EV + rb * NN;

    float p[7];
    float sum = 0.f;
    #pragma unroll
    for (int r = 0; r < 7; r++) {
        int k = lane + 32*r;
        if (k < NN) { p[r] = EA[k] * EB[k]; sum += p[r]; }
        else p[r] = 0.f;
    }
    #pragma unroll
    for (int o = 16; o > 0; o >>= 1)
        sum += __shfl_xor_sync(0xffffffffu, sum, o);
    float inv = 1.f / sum;

    if (side == 1) {
        #pragma unroll
        for (int r = 0; r < 7; r++) {
            int k = lane + 32*r;
            if (k < NN) s[h*200 + k] = p[r] * inv;
        }
    }
    __syncthreads();
    if (side == 0) {
        #pragma unroll
        for (int r = 0; r < 7; r++) {
            int k = lane + 32*r;
            if (k < NN) s[h*200 + k] = p[r] * inv + s[h*200 + k];
        }
    }
    __syncthreads();
    // coalesced half2 write
    __half2* dst = (__half2*)(g_Pch + (size_t)b * 800);
    for (int t2 = threadIdx.x; t2 < 400; t2 += 256)
        dst[t2] = __floats2half2_rn(s[2*t2], s[2*t2 + 1]);
}

// ---------------- VW (fp16) ----------------
__global__ void k_vw(const float* __restrict__ W3)
{
    int row = blockIdx.x, t = threadIdx.x;  // 128 threads
    int h = row / NN, k = row % NN;
    __shared__ float vr[HDd];
    if (t < HDd) vr[t] = g_vh[(h*NN + k)*HDd + t];
    __syncthreads();
    for (int c = t; c < DMm; c += 128) {
        float acc = 0.f;
        for (int d = 0; d < HDd; d++) acc += vr[d] * W3[(h*HDd + d)*DMm + c];
        g_VWh[row*DMm + c] = __float2half_rn(acc);
    }
}

// ---------------- fp16 MMA GEMM: S = Pc(40000x800) @ VW(800x472) + 2*b3 ----------------
#define BMt 128
#define BNt 64
#define BKt 32
#define A_STRIDE 40
#define B_STRIDE 72
#define A_BYTES  (BMt * A_STRIDE * 2)
#define B_BYTES  (BKt * B_STRIDE * 2)
#define STG_BYTES (A_BYTES + B_BYTES)
#define KT 25

__device__ __forceinline__ void cp_async16(unsigned dst, const void* src, int src_bytes) {
    asm volatile("cp.async.cg.shared.global [%0], [%1], 16, %2;\n"
                 :: "r"(dst), "l"(src), "r"(src_bytes));
}
__device__ __forceinline__ void cp_commit() {
    asm volatile("cp.async.commit_group;\n");
}
__device__ __forceinline__ void cp_wait1() {
    asm volatile("cp.async.wait_group 1;\n");
}
__device__ __forceinline__ void ldmA4(unsigned* r, unsigned addr) {
    asm volatile("ldmatrix.sync.aligned.m8n8.x4.shared.b16 {%0,%1,%2,%3}, [%4];"
                 : "=r"(r[0]), "=r"(r[1]), "=r"(r[2]), "=r"(r[3]) : "r"(addr));
}
__device__ __forceinline__ void ldmBT4(unsigned* r, unsigned addr) {
    asm volatile("ldmatrix.sync.aligned.m8n8.x4.trans.shared.b16 {%0,%1,%2,%3}, [%4];"
                 : "=r"(r[0]), "=r"(r[1]), "=r"(r[2]), "=r"(r[3]) : "r"(addr));
}
__device__ __forceinline__ void mma_f16(float* c, const unsigned* a, const unsigned* b) {
    asm volatile("mma.sync.aligned.m16n8k16.row.col.f32.f16.f16.f32 "
                 "{%0,%1,%2,%3},{%4,%5,%6,%7},{%8,%9},{%0,%1,%2,%3};"
                 : "+f"(c[0]), "+f"(c[1]), "+f"(c[2]), "+f"(c[3])
                 : "r"(a[0]), "r"(a[1]), "r"(a[2]), "r"(a[3]), "r"(b[0]), "r"(b[1]));
}

__device__ __forceinline__ void load_stage(unsigned sbase, int stage, int k0,
                                           int bm, int bn, int t)
{
    unsigned sa = sbase + stage * STG_BYTES;
    unsigned sb = sa + A_BYTES;
    #pragma unroll
    for (int p = 0; p < 2; p++) {
        int li = t + p * 256;
        int row = li >> 2, ch = li & 3;
        int grow = bm + row;
        bool ok = (grow < 40000);
        const __half* src = g_Pch + (size_t)(ok ? grow : 0) * 800 + k0 + ch * 8;
        cp_async16(sa + (unsigned)(row * A_STRIDE + ch * 8) * 2, src, ok ? 16 : 0);
    }
    {
        int k = t >> 3, ch = t & 7;
        int col = bn + ch * 8;
        int rem = DMm - col;
        int sz = (rem >= 8) ? 16 : ((rem > 0) ? rem * 2 : 0);
        const __half* src = g_VWh + (size_t)(k0 + k) * DMm + ((col < DMm) ? col : 0);
        cp_async16(sb + (unsigned)(k * B_STRIDE + ch * 8) * 2, src, sz);
    }
}

__global__ __launch_bounds__(256) void k_mma(const float* __restrict__ B3,
                                             float* __restrict__ out)
{
    __shared__ __align__(16) unsigned char smem[3 * STG_BYTES];
    unsigned sbase = (unsigned)__cvta_generic_to_shared(smem);

    int t = threadIdx.x;
    int w = t >> 5, lane = t & 31;
    int wm = (w & 3) * 32;
    int wn = (w >> 2) * 32;
    int bm = blockIdx.y * BMt, bn = blockIdx.x * BNt;

    float acc[2][4][4];
    #pragma unroll
    for (int mm = 0; mm < 2; mm++)
        #pragma unroll
        for (int nn = 0; nn < 4; nn++)
            #pragma unroll
            for (int q = 0; q < 4; q++) acc[mm][nn][q] = 0.f;

    int arow = wm + (lane & 15);
    int acb  = (lane >> 4) * 8;
    int bkl  = (lane & 7) + (lane & 8);
    int bnl  = wn + ((lane >> 4) * 8);

    load_stage(sbase, 0, 0, bm, bn, t);  cp_commit();
    load_stage(sbase, 1, 32, bm, bn, t); cp_commit();

    for (int kt = 0; kt < KT; kt++) {
        cp_wait1();
        __syncthreads();
        if (kt + 2 < KT) load_stage(sbase, (kt + 2) % 3, (kt + 2) * BKt, bm, bn, t);
        cp_commit();
        unsigned sa = sbase + (kt % 3) * STG_BYTES;
        unsigned sb = sa + A_BYTES;
        #pragma unroll
        for (int ks = 0; ks < 2; ks++) {
            unsigned af[2][4], bf[2][4];
            ldmA4(af[0], sa + (unsigned)((arow)      * A_STRIDE + ks * 16 + acb) * 2);
            ldmA4(af[1], sa + (unsigned)((arow + 16) * A_STRIDE + ks * 16 + acb) * 2);
            ldmBT4(bf[0], sb + (unsigned)((ks * 16 + bkl) * B_STRIDE + bnl) * 2);
            ldmBT4(bf[1], sb + (unsigned)((ks * 16 + bkl) * B_STRIDE + bnl + 16) * 2);
            #pragma unroll
            for (int mm = 0; mm < 2; mm++) {
                mma_f16(acc[mm][0], af[mm], bf[0] + 0);
                mma_f16(acc[mm][1], af[mm], bf[0] + 2);
                mma_f16(acc[mm][2], af[mm], bf[1] + 0);
                mma_f16(acc[mm][3], af[mm], bf[1] + 2);
            }
        }
        __syncthreads();
    }

    int r0 = bm + wm + (lane >> 2);
    int c0 = bn + wn + (lane & 3) * 2;
    #pragma unroll
    for (int mm = 0; mm < 2; mm++) {
        int rbase = r0 + mm * 16;
        #pragma unroll
        for (int nn = 0; nn < 4; nn++) {
            int c = c0 + nn * 8;
            if (c < DMm) {
                float b3a = 2.f * B3[c], b3b = 2.f * B3[c + 1];
                if (rbase < 40000) {
                    float2 v = make_float2(acc[mm][nn][0] + b3a, acc[mm][nn][1] + b3b);
                    *(float2*)&out[(size_t)rbase * DMm + c] = v;
                }
                if (rbase + 8 < 40000) {
                    float2 v = make_float2(acc[mm][nn][2] + b3a, acc[mm][nn][3] + b3b);
                    *(float2*)&out[(size_t)(rbase + 8) * DMm + c] = v;
                }
            }
        }
    }
}

// ---------------- Q_sa: warp per row ----------------
__global__ __launch_bounds__(256) void k_qsa(const float* __restrict__ v1w,
                                             const float* __restrict__ v1b,
                                             const float* __restrict__ v2w,
                                             const float* __restrict__ v2b,
                                             const float* __restrict__ S,
                                             float* __restrict__ qout)
{
    int wid = threadIdx.x >> 5, lane = threadIdx.x & 31;
    int b = blockIdx.x * 8 + wid;
    const float* Srow = S + (size_t)b * DMm;
    float acc0 = 0.f, acc1 = 0.f;
    for (int r = 0; r < DMm; r += 4) {
        float4 s4 = *(const float4*)(Srow + r);
        acc0 += s4.x * v1w[(r + 0) * 48 + lane];
        acc0 += s4.y * v1w[(r + 1) * 48 + lane];
        acc0 += s4.z * v1w[(r + 2) * 48 + lane];
        acc0 += s4.w * v1w[(r + 3) * 48 + lane];
        if (lane < 16) {
            acc1 += s4.x * v1w[(r + 0) * 48 + 32 + lane];
            acc1 += s4.y * v1w[(r + 1) * 48 + 32 + lane];
            acc1 += s4.z * v1w[(r + 2) * 48 + 32 + lane];
            acc1 += s4.w * v1w[(r + 3) * 48 + 32 + lane];
        }
    }
    float val = fmaxf(acc0 + v1b[lane], 0.f) * v2w[lane];
    if (lane < 16)
        val += fmaxf(acc1 + v1b[32 + lane], 0.f) * v2w[32 + lane];
    #pragma unroll
    for (int o = 16; o > 0; o >>= 1)
        val += __shfl_xor_sync(0xffffffffu, val, o);
    if (lane == 0) qout[b] = val + v2b[0];
}

// ---------------- tail: copy h, h_full into output ----------------
__global__ void k_tail(float* __restrict__ out)
{
    int idx = blockIdx.x * blockDim.x + threadIdx.x;
    if (idx < NN*HIDN) out[H_OFF + idx] = g_hA[idx];
    else if (idx < NN*HIDN + NN*HDd) {
        int j = idx - NN*HIDN;
        out[HF_OFF + j] = g_hfull[j];
    }
}

// ---------------- launcher ----------------
extern "C" void kernel_launch(void* const* d_in, const int* in_sizes, int n_in,
                              void* d_out, int out_size)
{
    const float* x     = (const float*)d_in[0];
    const float* label = (const float*)d_in[1];
    const float* h0    = (const float*)d_in[2];
    const float* w     = (const float*)d_in[3];
    const float* dv    = (const float*)d_in[4];
    const float* l0w   = (const float*)d_in[5];
    const float* l0b   = (const float*)d_in[6];
    const float* l1w   = (const float*)d_in[7];
    const float* l1b   = (const float*)d_in[8];
    const float* l2w   = (const float*)d_in[9];
    const float* l2b   = (const float*)d_in[10];
    const float* l3w   = (const float*)d_in[11];
    const float* l3b   = (const float*)d_in[12];
    const float* l4w   = (const float*)d_in[13];
    const float* l4b   = (const float*)d_in[14];
    const float* l5w   = (const float*)d_in[15];
    const float* l5b   = (const float*)d_in[16];
    const float* W0    = (const float*)d_in[17];
    const float* B0    = (const float*)d_in[18];
    const float* W1    = (const float*)d_in[19];
    const float* B1    = (const float*)d_in[20];
    const float* W3    = (const float*)d_in[21];
    const float* B3    = (const float*)d_in[22];
    const float* v1w   = (const float*)d_in[23];
    const float* v1b   = (const float*)d_in[24];
    const float* v2w   = (const float*)d_in[25];
    const float* v2b   = (const float*)d_in[26];
    const int* gnn_step = (const int*)d_in[27];
    const int* remain   = (const int*)d_in[29];
    float* out = (float*)d_out;

    k_prep<<<NN, 128>>>(x, label, h0, w, dv, l0w, l0b, l1w, l1b, l2b, l3b, l4w, l4b, l5w, l5b);
    for (int it = 0; it < 8; it++)
        k_gcn<<<NN, HIDN>>>(w, l2w, l3w, gnn_step, it);
    k_hfull<<<NN, 128>>>(x, label, remain);
    k_gct<<<KK, HDd>>>(label);
    k_lg<<<NN, HDd>>>(label);
    k_wsum<<<(HDd*DMm + 255)/256, 256>>>(W0, W1);
    k_proj<<<NN, 128>>>(W0, B0, B1);
    dim3 guv(NN, NHh);
    k_uv<<<guv, 256>>>();
    k_expuv<<<100, 256>>>();
    k_vw<<<NHh*NN, 128>>>(W3);
    k_prob<<<40000, 256>>>();
    dim3 gs(8, 313);
    k_mma<<<gs, 256>>>(B3, out);
    k_qsa<<<5000, 256>>>(v1w, v1b, v2w, v2b, out, out + Q_OFF);
    k_tail<<<(NN*HIDN + NN*HDd + 255)/256, 256>>>(out);
}

// round 8
// speedup vs baseline: 3.1752x; 1.1710x over previous
#include <cuda_runtime.h>
#include <cuda_fp16.h>
#include <math.h>

#define NN   200
#define DEGN 199
#define KK   20
#define MMg  10
#define HIDN 96
#define NHh  4
#define HDd  118
#define DMm  472
#define AJRn 30

#define S_OFF  0
#define H_OFF  18880000
#define HF_OFF 18899200
#define Q_OFF  18922800

// ---------------- static device scratch ----------------
__device__ float g_stat[NN*HIDN];
__device__ float g_den1[NN], g_den2[NN];
__device__ float g_hA[NN*HIDN], g_hB[NN*HIDN];
__device__ float g_hfull[NN*HDd];
__device__ float g_gcT[KK*HDd];
__device__ float g_lg[NN*HDd];
__device__ float g_W0s[HDd*DMm], g_W1s[HDd*DMm];
__device__ float g_P1[NN*DMm], g_P2[NN*DMm];
__device__ float g_khs[NHh*HDd*NN];     // [h][d][k]
__device__ float g_vh[NHh*NN*HDd];      // [h][k][d]
__device__ float g_U[NN*NHh*NN], g_V[NN*NHh*NN];   // [(i*4+h)][k]
__device__ float g_EU[NN*NHh*NN], g_EV[NN*NHh*NN]; // exp(U - rowmax), exp(V - rowmax)
__device__ __half g_VWh[800*DMm];       // [h*200+k][c]  fp16
__device__ __half g_Pch[40000u*800u];   // 64 MB fp16

// ---------------- prep: edge sorts + static part of GCN ----------------
__global__ void k_prep(const float* __restrict__ x, const float* __restrict__ label,
                       const float* __restrict__ h0,
                       const float* __restrict__ w, const float* __restrict__ dv,
                       const float* __restrict__ l0w, const float* __restrict__ l0b,
                       const float* __restrict__ l1w, const float* __restrict__ l1b,
                       const float* __restrict__ l2b, const float* __restrict__ l3b,
                       const float* __restrict__ l4w, const float* __restrict__ l4b,
                       const float* __restrict__ l5w, const float* __restrict__ l5b)
{
    int i = blockIdx.x; int t = threadIdx.x;  // 128 threads
    int gi = i / MMg;
    __shared__ float a1[256], a2[256];
    __shared__ float red1[128], red2[128];
    float p1 = 0.f, p2 = 0.f;
    for (int e = t; e < 256; e += 128) {
        float v1 = -1e30f, v2 = -1e30f;
        if (e < DEGN) {
            int s = (e < i) ? e : e + 1;
            bool sm = (s / MMg) == gi;
            float d0 = dv[i*DEGN + e];
            float w0 = w[i*DEGN + e];
            if (sm) { v2 = d0; p2 += w0; } else { v1 = d0; p1 += w0; }
        }
        a1[e] = v1; a2[e] = v2;
    }
    red1[t] = p1; red2[t] = p2;
    __syncthreads();
    for (int off = 64; off > 0; off >>= 1) {
        if (t < off) { red1[t] += red1[t+off]; red2[t] += red2[t+off]; }
        __syncthreads();
    }
    if (t == 0) { g_den1[i] = red1[0]; g_den2[i] = red2[0]; }
    for (int ksz = 2; ksz <= 256; ksz <<= 1) {
        for (int jsz = ksz >> 1; jsz > 0; jsz >>= 1) {
            __syncthreads();
            for (int e = t; e < 256; e += 128) {
                int p = e ^ jsz;
                if (p > e) {
                    bool desc = ((e & ksz) == 0);
                    float av = a1[e], bv = a1[p];
                    if (desc ? (av < bv) : (av > bv)) { a1[e] = bv; a1[p] = av; }
                    float cv = a2[e], ev = a2[p];
                    if (desc ? (cv < ev) : (cv > ev)) { a2[e] = ev; a2[p] = cv; }
                }
            }
        }
    }
    __syncthreads();
    if (t < HIDN) {
        float acc = l0b[t] + l1b[t] + l2b[t] + l3b[t] + l4b[t] + l5b[t];
        acc += x[i*2+0]*l0w[0*HIDN+t] + x[i*2+1]*l0w[1*HIDN+t];
        for (int g = 0; g < KK; g++) acc += label[i*KK+g]*l1w[g*HIDN+t];
        for (int r = 0; r < AJRn; r++) acc += a1[r]*l4w[r*HIDN+t];
        for (int r = 0; r < MMg-1; r++) acc += a2[r]*l5w[r*HIDN+t];
        g_stat[i*HIDN+t] = acc;
        g_hA[i*HIDN+t] = h0[i*HIDN+t];
    }
}

// ---------------- one GCN iteration ----------------
__global__ void k_gcn(const float* __restrict__ w,
                      const float* __restrict__ l2w, const float* __restrict__ l3w,
                      const int* __restrict__ gnn_step, int iter)
{
    int i = blockIdx.x, c = threadIdx.x;  // 96 threads
    const float* hin  = (iter & 1) ? g_hB : g_hA;
    float*       hout = (iter & 1) ? g_hA : g_hB;
    if (!(iter < *gnn_step)) { hout[i*HIDN+c] = hin[i*HIDN+c]; return; }
    int gi = i / MMg;
    float acc1 = 0.f, acc2 = 0.f;
    __shared__ float sn1[HIDN], sn2[HIDN];
    for (int s = 0; s < NN; s++) {
        if (s == i) continue;
        int j = s - (s > i);
        float wv = w[i*DEGN + j];
        float hv = hin[s*HIDN + c];
        if (s / MMg == gi) acc2 += wv*hv; else acc1 += wv*hv;
    }
    sn1[c] = acc1 / g_den1[i];
    sn2[c] = acc2 / g_den2[i];
    __syncthreads();
    float o = g_stat[i*HIDN + c];
    for (int r = 0; r < HIDN; r++)
        o += sn1[r]*l2w[r*HIDN+c] + sn2[r]*l3w[r*HIDN+c];
    hout[i*HIDN + c] = fmaxf(o, 0.f);
}

// ---------------- h_full = [h + pe, x, label] ----------------
__global__ void k_hfull(const float* __restrict__ x, const float* __restrict__ label,
                        const int* __restrict__ remain)
{
    int i = blockIdx.x, t = threadIdx.x;
    if (t >= HDd) return;
    float v;
    if (t < HIDN) {
        int p = *remain;
        int k2 = t & ~1;
        double div = exp(-(double)k2 * log(10000.0) / (double)HIDN);
        double ang = (double)p * div;
        v = g_hA[i*HIDN + t] + (float)((t & 1) ? cos(ang) : sin(ang));
    } else if (t < HIDN + 2) v = x[i*2 + (t - HIDN)];
    else v = label[i*KK + (t - HIDN - 2)];
    g_hfull[i*HDd + t] = v;
}

__global__ void k_gct(const float* __restrict__ label)
{
    int g = blockIdx.x, dd = threadIdx.x;
    float acc = 0.f;
    for (int i = 0; i < NN; i++) acc += label[i*KK + g] * g_hfull[i*HDd + dd];
    g_gcT[g*HDd + dd] = acc * 0.1f;
}

__global__ void k_lg(const float* __restrict__ label)
{
    int i = blockIdx.x, dd = threadIdx.x;
    float acc = 0.f;
    for (int g = 0; g < KK; g++) acc += label[i*KK + g] * g_gcT[g*HDd + dd];
    g_lg[i*HDd + dd] = acc;
}

__global__ void k_wsum(const float* __restrict__ W0, const float* __restrict__ W1)
{
    int idx = blockIdx.x * blockDim.x + threadIdx.x;
    if (idx >= HDd*DMm) return;
    int d = idx / DMm, c = idx % DMm;
    g_W0s[idx] = W0[d*DMm+c] + W0[(118+d)*DMm+c] + W0[(236+d)*DMm+c] + W0[(354+d)*DMm+c];
    g_W1s[idx] = W1[d*DMm+c] + W1[(118+d)*DMm+c] + W1[(236+d)*DMm+c] + W1[(354+d)*DMm+c];
}

// ---------------- per-node projections ----------------
__global__ void k_proj(const float* __restrict__ W0, const float* __restrict__ B0,
                       const float* __restrict__ B1)
{
    int i = blockIdx.x, t = threadIdx.x;  // 128 threads
    __shared__ float hf[HDd], lgs[HDd];
    if (t < HDd) { hf[t] = g_hfull[i*HDd + t]; lgs[t] = g_lg[i*HDd + t]; }
    __syncthreads();
    const float scale = 1.0f / sqrtf((float)HDd);
    for (int c = t; c < DMm; c += 128) {
        float p1 = B0[c], p2 = 0.f, kf = B0[c], vf = B1[c];
        for (int d = 0; d < HDd; d++) {
            float hv = hf[d], lv = lgs[d];
            p1 += hv * W0[d*DMm + c]       + lv * W0[(236+d)*DMm + c];
            p2 += hv * W0[(118+d)*DMm + c] + lv * W0[(354+d)*DMm + c];
            kf += hv * g_W0s[d*DMm + c];
            vf += hv * g_W1s[d*DMm + c];
        }
        g_P1[i*DMm + c] = p1;
        g_P2[i*DMm + c] = p2;
        int h = c / HDd, dd = c % HDd;
        g_khs[(h*HDd + dd)*NN + i] = kf * scale;
        g_vh[(h*NN + i)*HDd + dd] = vf;
    }
}

// ---------------- U/V score components ----------------
__global__ void k_uv()
{
    int i = blockIdx.x, h = blockIdx.y, t = threadIdx.x;  // 256 threads
    __shared__ float s1[HDd], s2[HDd];
    if (t < HDd) {
        s1[t] = g_P1[i*DMm + h*HDd + t];
        s2[t] = g_P2[i*DMm + h*HDd + t];
    }
    __syncthreads();
    if (t < NN) {
        float u = 0.f, v = 0.f;
        for (int d = 0; d < HDd; d++) {
            float kv = g_khs[(h*HDd + d)*NN + t];
            u += s1[d] * kv;
            v += s2[d] * kv;
        }
        g_U[(i*NHh + h)*NN + t] = u;
        g_V[(i*NHh + h)*NN + t] = v;
    }
}

// ---------------- EU/EV: rowwise exp(x - rowmax) over the 800 U,V rows ----------------
__global__ void k_expuv()
{
    int row = blockIdx.x * 8 + (threadIdx.x >> 5);   // 0..799
    int lane = threadIdx.x & 31;
    const float* Ur = g_U + row * NN;
    const float* Vr = g_V + row * NN;
    float u[7], v[7];
    float mu = -1e30f, mv = -1e30f;
    #pragma unroll
    for (int r = 0; r < 7; r++) {
        int k = lane + 32*r;
        if (k < NN) {
            u[r] = Ur[k]; v[r] = Vr[k];
            mu = fmaxf(mu, u[r]); mv = fmaxf(mv, v[r]);
        } else { u[r] = -1e30f; v[r] = -1e30f; }
    }
    #pragma unroll
    for (int o = 16; o > 0; o >>= 1) {
        mu = fmaxf(mu, __shfl_xor_sync(0xffffffffu, mu, o));
        mv = fmaxf(mv, __shfl_xor_sync(0xffffffffu, mv, o));
    }
    #pragma unroll
    for (int r = 0; r < 7; r++) {
        int k = lane + 32*r;
        if (k < NN) {
            g_EU[row * NN + k] = __expf(u[r] - mu);
            g_EV[row * NN + k] = __expf(v[r] - mv);
        }
    }
}

// ---------------- pair-softmax via separable exps ----------------
__global__ __launch_bounds__(256) void k_prob()
{
    int b = blockIdx.x;
    int i = b / NN, j = b % NN;
    int w = threadIdx.x >> 5;
    int lane = threadIdx.x & 31;
    int h = w & 3, side = w >> 2;
    __shared__ float s[800];

    int ra = (side ? j : i) * NHh + h;   // EU row
    int rb = (side ? i : j) * NHh + h;   // EV row
    const float* EA = g_EU + ra * NN;
    const float* EB = g_EV + rb * NN;

    float p[7];
    float sum = 0.f;
    #pragma unroll
    for (int r = 0; r < 7; r++) {
        int k = lane + 32*r;
        if (k < NN) { p[r] = EA[k] * EB[k]; sum += p[r]; }
        else p[r] = 0.f;
    }
    #pragma unroll
    for (int o = 16; o > 0; o >>= 1)
        sum += __shfl_xor_sync(0xffffffffu, sum, o);
    float inv = 1.f / sum;

    if (side == 1) {
        #pragma unroll
        for (int r = 0; r < 7; r++) {
            int k = lane + 32*r;
            if (k < NN) s[h*200 + k] = p[r] * inv;
        }
    }
    __syncthreads();
    if (side == 0) {
        #pragma unroll
        for (int r = 0; r < 7; r++) {
            int k = lane + 32*r;
            if (k < NN) s[h*200 + k] = p[r] * inv + s[h*200 + k];
        }
    }
    __syncthreads();
    __half2* dst = (__half2*)(g_Pch + (size_t)b * 800);
    for (int t2 = threadIdx.x; t2 < 400; t2 += 256)
        dst[t2] = __floats2half2_rn(s[2*t2], s[2*t2 + 1]);
}

// ---------------- VW (fp16) ----------------
__global__ void k_vw(const float* __restrict__ W3)
{
    int row = blockIdx.x, t = threadIdx.x;  // 128 threads
    int h = row / NN, k = row % NN;
    __shared__ float vr[HDd];
    if (t < HDd) vr[t] = g_vh[(h*NN + k)*HDd + t];
    __syncthreads();
    for (int c = t; c < DMm; c += 128) {
        float acc = 0.f;
        for (int d = 0; d < HDd; d++) acc += vr[d] * W3[(h*HDd + d)*DMm + c];
        g_VWh[row*DMm + c] = __float2half_rn(acc);
    }
}

// ---------------- fp16 MMA GEMM: S = Pc(40000x800) @ VW(800x472) + 2*b3 ----------------
#define BMt 128
#define BNt 64
#define BKt 32
#define A_STRIDE 40
#define B_STRIDE 72
#define A_BYTES  (BMt * A_STRIDE * 2)
#define B_BYTES  (BKt * B_STRIDE * 2)
#define STG_BYTES (A_BYTES + B_BYTES)
#define KT 25

__device__ __forceinline__ void cp_async16(unsigned dst, const void* src, int src_bytes) {
    asm volatile("cp.async.cg.shared.global [%0], [%1], 16, %2;\n"
                 :: "r"(dst), "l"(src), "r"(src_bytes));
}
__device__ __forceinline__ void cp_commit() {
    asm volatile("cp.async.commit_group;\n");
}
__device__ __forceinline__ void cp_wait1() {
    asm volatile("cp.async.wait_group 1;\n");
}
__device__ __forceinline__ void ldmA4(unsigned* r, unsigned addr) {
    asm volatile("ldmatrix.sync.aligned.m8n8.x4.shared.b16 {%0,%1,%2,%3}, [%4];"
                 : "=r"(r[0]), "=r"(r[1]), "=r"(r[2]), "=r"(r[3]) : "r"(addr));
}
__device__ __forceinline__ void ldmBT4(unsigned* r, unsigned addr) {
    asm volatile("ldmatrix.sync.aligned.m8n8.x4.trans.shared.b16 {%0,%1,%2,%3}, [%4];"
                 : "=r"(r[0]), "=r"(r[1]), "=r"(r[2]), "=r"(r[3]) : "r"(addr));
}
__device__ __forceinline__ void mma_f16(float* c, const unsigned* a, const unsigned* b) {
    asm volatile("mma.sync.aligned.m16n8k16.row.col.f32.f16.f16.f32 "
                 "{%0,%1,%2,%3},{%4,%5,%6,%7},{%8,%9},{%0,%1,%2,%3};"
                 : "+f"(c[0]), "+f"(c[1]), "+f"(c[2]), "+f"(c[3])
                 : "r"(a[0]), "r"(a[1]), "r"(a[2]), "r"(a[3]), "r"(b[0]), "r"(b[1]));
}

__device__ __forceinline__ void load_stage(unsigned sbase, int stage, int k0,
                                           int bm, int bn, int t)
{
    unsigned sa = sbase + stage * STG_BYTES;
    unsigned sb = sa + A_BYTES;
    #pragma unroll
    for (int p = 0; p < 2; p++) {
        int li = t + p * 256;
        int row = li >> 2, ch = li & 3;
        int grow = bm + row;
        bool ok = (grow < 40000);
        const __half* src = g_Pch + (size_t)(ok ? grow : 0) * 800 + k0 + ch * 8;
        cp_async16(sa + (unsigned)(row * A_STRIDE + ch * 8) * 2, src, ok ? 16 : 0);
    }
    {
        int k = t >> 3, ch = t & 7;
        int col = bn + ch * 8;
        int rem = DMm - col;
        int sz = (rem >= 8) ? 16 : ((rem > 0) ? rem * 2 : 0);
        const __half* src = g_VWh + (size_t)(k0 + k) * DMm + ((col < DMm) ? col : 0);
        cp_async16(sb + (unsigned)(k * B_STRIDE + ch * 8) * 2, src, sz);
    }
}

__global__ __launch_bounds__(256) void k_mma(const float* __restrict__ B3,
                                             float* __restrict__ out)
{
    __shared__ __align__(16) unsigned char smem[3 * STG_BYTES];
    unsigned sbase = (unsigned)__cvta_generic_to_shared(smem);

    int t = threadIdx.x;
    int w = t >> 5, lane = t & 31;
    int wm = (w & 3) * 32;
    int wn = (w >> 2) * 32;
    int bm = blockIdx.y * BMt, bn = blockIdx.x * BNt;

    float acc[2][4][4];
    #pragma unroll
    for (int mm = 0; mm < 2; mm++)
        #pragma unroll
        for (int nn = 0; nn < 4; nn++)
            #pragma unroll
            for (int q = 0; q < 4; q++) acc[mm][nn][q] = 0.f;

    int arow = wm + (lane & 15);
    int acb  = (lane >> 4) * 8;
    int bkl  = (lane & 7) + (lane & 8);
    int bnl  = wn + ((lane >> 4) * 8);

    load_stage(sbase, 0, 0, bm, bn, t);  cp_commit();
    load_stage(sbase, 1, 32, bm, bn, t); cp_commit();

    for (int kt = 0; kt < KT; kt++) {
        cp_wait1();
        __syncthreads();
        if (kt + 2 < KT) load_stage(sbase, (kt + 2) % 3, (kt + 2) * BKt, bm, bn, t);
        cp_commit();
        unsigned sa = sbase + (kt % 3) * STG_BYTES;
        unsigned sb = sa + A_BYTES;
        #pragma unroll
        for (int ks = 0; ks < 2; ks++) {
            unsigned af[2][4], bf[2][4];
            ldmA4(af[0], sa + (unsigned)((arow)      * A_STRIDE + ks * 16 + acb) * 2);
            ldmA4(af[1], sa + (unsigned)((arow + 16) * A_STRIDE + ks * 16 + acb) * 2);
            ldmBT4(bf[0], sb + (unsigned)((ks * 16 + bkl) * B_STRIDE + bnl) * 2);
            ldmBT4(bf[1], sb + (unsigned)((ks * 16 + bkl) * B_STRIDE + bnl + 16) * 2);
            #pragma unroll
            for (int mm = 0; mm < 2; mm++) {
                mma_f16(acc[mm][0], af[mm], bf[0] + 0);
                mma_f16(acc[mm][1], af[mm], bf[0] + 2);
                mma_f16(acc[mm][2], af[mm], bf[1] + 0);
                mma_f16(acc[mm][3], af[mm], bf[1] + 2);
            }
        }
        __syncthreads();
    }

    int r0 = bm + wm + (lane >> 2);
    int c0 = bn + wn + (lane & 3) * 2;
    #pragma unroll
    for (int mm = 0; mm < 2; mm++) {
        int rbase = r0 + mm * 16;
        #pragma unroll
        for (int nn = 0; nn < 4; nn++) {
            int c = c0 + nn * 8;
            if (c < DMm) {
                float b3a = 2.f * B3[c], b3b = 2.f * B3[c + 1];
                if (rbase < 40000) {
                    float2 v = make_float2(acc[mm][nn][0] + b3a, acc[mm][nn][1] + b3b);
                    *(float2*)&out[(size_t)rbase * DMm + c] = v;
                }
                if (rbase + 8 < 40000) {
                    float2 v = make_float2(acc[mm][nn][2] + b3a, acc[mm][nn][3] + b3b);
                    *(float2*)&out[(size_t)(rbase + 8) * DMm + c] = v;
                }
            }
        }
    }
}

// ---------------- Q_sa: smem-tiled GEMM, 256 rows/block, 4x12 per thread ----------------
#define QROWS 256
#define QKT   32
__global__ __launch_bounds__(256) void k_qsa(const float* __restrict__ v1w,
                                             const float* __restrict__ v1b,
                                             const float* __restrict__ v2w,
                                             const float* __restrict__ v2b,
                                             const float* __restrict__ S,
                                             float* __restrict__ qout)
{
    __shared__ float sS[QKT][QROWS + 1];
    __shared__ float sW[QKT][48];

    int tid = threadIdx.x;
    int ty = tid >> 2;        // 0..63  -> 4 rows each
    int tx = tid & 3;         // 0..3   -> 12 cols each
    int base = blockIdx.x * QROWS;

    float acc[4][12];
    #pragma unroll
    for (int r = 0; r < 4; r++)
        #pragma unroll
        for (int c = 0; c < 12; c++) acc[r][c] = 0.f;

    for (int k0 = 0; k0 < DMm; k0 += QKT) {
        int TK = DMm - k0; if (TK > QKT) TK = QKT;   // 32 or 24 (both mult of 8)
        // load S tile transposed: sS[k][row]
        #pragma unroll
        for (int it = 0; it < 8; it++) {
            int idx = tid + it * 256;          // 0..2047
            int r = idx >> 3;                  // 0..255
            int c4 = idx & 7;                  // 0..7
            int k = c4 * 4;
            if (k < TK) {
                int grow = base + r;
                const float* src = S + (size_t)(grow < 40000 ? grow : 0) * DMm + k0 + k;
                float4 v = *(const float4*)src;
                sS[k + 0][r] = v.x; sS[k + 1][r] = v.y;
                sS[k + 2][r] = v.z; sS[k + 3][r] = v.w;
            }
        }
        // load W tile: sW[k][c]
        #pragma unroll
        for (int it = 0; it < 6; it++) {
            int idx = tid + it * 256;          // 0..1535
            int k = idx / 48, c = idx - k * 48;
            if (k < TK)
                sW[k][c] = v1w[(k0 + k) * 48 + c];
        }
        __syncthreads();
        for (int k = 0; k < TK; k++) {
            float a0 = sS[k][ty * 4 + 0];
            float a1 = sS[k][ty * 4 + 1];
            float a2 = sS[k][ty * 4 + 2];
            float a3 = sS[k][ty * 4 + 3];
            #pragma unroll
            for (int c = 0; c < 12; c++) {
                float wv = sW[k][tx * 12 + c];
                acc[0][c] += a0 * wv;
                acc[1][c] += a1 * wv;
                acc[2][c] += a2 * wv;
                acc[3][c] += a3 * wv;
            }
        }
        __syncthreads();
    }

    // epilogue: relu + dot with v2w, reduce over the 4 tx lanes
    float b1[12], w2[12];
    #pragma unroll
    for (int c = 0; c < 12; c++) {
        b1[c] = v1b[tx * 12 + c];
        w2[c] = v2w[tx * 12 + c];
    }
    float vb2 = v2b[0];
    #pragma unroll
    for (int r = 0; r < 4; r++) {
        float part = 0.f;
        #pragma unroll
        for (int c = 0; c < 12; c++)
            part += fmaxf(acc[r][c] + b1[c], 0.f) * w2[c];
        part += __shfl_xor_sync(0xffffffffu, part, 1);
        part += __shfl_xor_sync(0xffffffffu, part, 2);
        int row = base + ty * 4 + r;
        if (tx == 0 && row < 40000) qout[row] = part + vb2;
    }
}

// ---------------- tail: copy h, h_full into output ----------------
__global__ void k_tail(float* __restrict__ out)
{
    int idx = blockIdx.x * blockDim.x + threadIdx.x;
    if (idx < NN*HIDN) out[H_OFF + idx] = g_hA[idx];
    else if (idx < NN*HIDN + NN*HDd) {
        int j = idx - NN*HIDN;
        out[HF_OFF + j] = g_hfull[j];
    }
}

// ---------------- launcher ----------------
extern "C" void kernel_launch(void* const* d_in, const int* in_sizes, int n_in,
                              void* d_out, int out_size)
{
    const float* x     = (const float*)d_in[0];
    const float* label = (const float*)d_in[1];
    const float* h0    = (const float*)d_in[2];
    const float* w     = (const float*)d_in[3];
    const float* dv    = (const float*)d_in[4];
    const float* l0w   = (const float*)d_in[5];
    const float* l0b   = (const float*)d_in[6];
    const float* l1w   = (const float*)d_in[7];
    const float* l1b   = (const float*)d_in[8];
    const float* l2w   = (const float*)d_in[9];
    const float* l2b   = (const float*)d_in[10];
    const float* l3w   = (const float*)d_in[11];
    const float* l3b   = (const float*)d_in[12];
    const float* l4w   = (const float*)d_in[13];
    const float* l4b   = (const float*)d_in[14];
    const float* l5w   = (const float*)d_in[15];
    const float* l5b   = (const float*)d_in[16];
    const float* W0    = (const float*)d_in[17];
    const float* B0    = (const float*)d_in[18];
    const float* W1    = (const float*)d_in[19];
    const float* B1    = (const float*)d_in[20];
    const float* W3    = (const float*)d_in[21];
    const float* B3    = (const float*)d_in[22];
    const float* v1w   = (const float*)d_in[23];
    const float* v1b   = (const float*)d_in[24];
    const float* v2w   = (const float*)d_in[25];
    const float* v2b   = (const float*)d_in[26];
    const int* gnn_step = (const int*)d_in[27];
    const int* remain   = (const int*)d_in[29];
    float* out = (float*)d_out;

    k_prep<<<NN, 128>>>(x, label, h0, w, dv, l0w, l0b, l1w, l1b, l2b, l3b, l4w, l4b, l5w, l5b);
    for (int it = 0; it < 8; it++)
        k_gcn<<<NN, HIDN>>>(w, l2w, l3w, gnn_step, it);
    k_hfull<<<NN, 128>>>(x, label, remain);
    k_gct<<<KK, HDd>>>(label);
    k_lg<<<NN, HDd>>>(label);
    k_wsum<<<(HDd*DMm + 255)/256, 256>>>(W0, W1);
    k_proj<<<NN, 128>>>(W0, B0, B1);
    dim3 guv(NN, NHh);
    k_uv<<<guv, 256>>>();
    k_expuv<<<100, 256>>>();
    k_vw<<<NHh*NN, 128>>>(W3);
    k_prob<<<40000, 256>>>();
    dim3 gs(8, 313);
    k_mma<<<gs, 256>>>(B3, out);
    k_qsa<<<157, 256>>>(v1w, v1b, v2w, v2b, out, out + Q_OFF);
    k_tail<<<(NN*HIDN + NN*HDd + 255)/256, 256>>>(out);
}